// round 15
// baseline (speedup 1.0000x reference)
#include <cuda_runtime.h>
#include <cuda_fp16.h>
#include <math.h>
#include <stdint.h>

#define Bn 8
#define Tn 2048
#define Cn 768
#define Hn 12
#define KSEL 1024
#define DFF 3072
#define BT (Bn*Tn)      /* 16384 */
#define BKn (Bn*KSEL)   /* 8192 */
#define G3C (3*Cn)      /* 2304 */

typedef unsigned long long ull;

// ---------------- f32x2 packed helpers --------------------------------------
__device__ __forceinline__ ull pk2(float x, float y) {
    ull r; asm("mov.b64 %0, {%1, %2};" : "=l"(r) : "f"(x), "f"(y)); return r;
}
__device__ __forceinline__ void fma2(ull &acc, ull a, ull b) {
    asm("fma.rn.f32x2 %0, %1, %2, %0;" : "+l"(acc) : "l"(a), "l"(b));
}
__device__ __forceinline__ float2 upk2(ull v) {
    float2 r; asm("mov.b64 {%0, %1}, %2;" : "=f"(r.x), "=f"(r.y) : "l"(v)); return r;
}
__device__ __forceinline__ unsigned pkh2(float a, float b) {
    __half2 h = __floats2half2_rn(a, b);
    return *reinterpret_cast<unsigned*>(&h);
}

// ---------------- cp.async / smem helpers ------------------------------------
__device__ __forceinline__ uint32_t smem_u32(const void* p) {
    uint32_t a; asm("{ .reg .u64 t; cvta.to.shared.u64 t, %1; cvt.u32.u64 %0, t; }"
                    : "=r"(a) : "l"(p));
    return a;
}
__device__ __forceinline__ void cp16(uint32_t saddr, const void* gaddr) {
    asm volatile("cp.async.cg.shared.global [%0], [%1], 16;"
                 :: "r"(saddr), "l"(__cvta_generic_to_global(gaddr)));
}
__device__ __forceinline__ void cp_commit() { asm volatile("cp.async.commit_group;"); }
template<int N>
__device__ __forceinline__ void cp_waitg() {
    asm volatile("cp.async.wait_group %0;" :: "n"(N) : "memory");
}
__device__ __forceinline__ void ldmx4(unsigned &r0, unsigned &r1, unsigned &r2,
                                      unsigned &r3, uint32_t addr) {
    asm volatile("ldmatrix.sync.aligned.m8n8.x4.shared.b16 {%0,%1,%2,%3}, [%4];"
                 : "=r"(r0), "=r"(r1), "=r"(r2), "=r"(r3) : "r"(addr));
}
__device__ __forceinline__ void ldmx4t(unsigned &r0, unsigned &r1, unsigned &r2,
                                       unsigned &r3, uint32_t addr) {
    asm volatile("ldmatrix.sync.aligned.m8n8.x4.trans.shared.b16 {%0,%1,%2,%3}, [%4];"
                 : "=r"(r0), "=r"(r1), "=r"(r2), "=r"(r3) : "r"(addr));
}
__device__ __forceinline__ void mma16816(float* d, unsigned a0, unsigned a1,
                                         unsigned a2, unsigned a3,
                                         unsigned b0, unsigned b1) {
    asm volatile("mma.sync.aligned.m16n8k16.row.col.f32.f16.f16.f32 "
                 "{%0,%1,%2,%3}, {%4,%5,%6,%7}, {%8,%9}, {%0,%1,%2,%3};"
                 : "+f"(d[0]), "+f"(d[1]), "+f"(d[2]), "+f"(d[3])
                 : "r"(a0), "r"(a1), "r"(a2), "r"(a3), "r"(b0), "r"(b1));
}
// release-reduce arrival + acquire poll (GPU scope)
__device__ __forceinline__ void red_release_add(unsigned* addr, unsigned v) {
    asm volatile("red.release.gpu.global.add.u32 [%0], %1;"
                 :: "l"(addr), "r"(v) : "memory");
}
__device__ __forceinline__ unsigned ld_acquire(const unsigned* addr) {
    unsigned v;
    asm volatile("ld.acquire.gpu.global.u32 %0, [%1];" : "=r"(v) : "l"(addr) : "memory");
    return v;
}

// ---------------- scratch -----------------------------------------------------
__device__ float g_xi[(size_t)BT*G3C];     // xi; later reused as half hlnr
__device__ float g_hrnn[(size_t)BT*Cn];
__device__ float g_hstate[Bn*Cn];
__device__ float g_energy[BT];
__device__ int   g_idx[BKn];
__device__ int   g_selmap[BT];
__device__ __half g_xsel_h[(size_t)BKn*Cn];
__device__ float g_gsel[BKn];
__device__ __half g_qkv_h[(size_t)BKn*G3C];
__device__ __half g_y_h[(size_t)BKn*Cn];
__device__ float g_weighted[(size_t)BKn*Cn];
__device__ float g_hln[(size_t)BT*Cn];
__device__ __half g_mid_h[(size_t)BT*DFF];
__device__ __half g_wscr_h[7077888];       // half weights: qkv|proj|ffn1|ffn2
__device__ __half g_xhi[(size_t)BT*Cn];
__device__ __half g_xlo[(size_t)BT*Cn];
__device__ __half g_wih_hi[(size_t)G3C*Cn];
__device__ __half g_wih_lo[(size_t)G3C*Cn];
__device__ unsigned g_bars[64];            // 2 group barriers, 128B apart
__device__ int g_active;

#define WOFF_QKV  0
#define WOFF_PROJ 1769472
#define WOFF_FFN1 2359296
#define WOFF_FFN2 4718592
#define WTOTAL    7077888

// ---------------- init --------------------------------------------------------
__global__ void init_kernel() {
    int tid = blockIdx.x * blockDim.x + threadIdx.x;
    if (tid == 0) g_active = 0;
    if (tid < 64) g_bars[tid] = 0u;
    for (int i = tid; i < Bn*Cn; i += gridDim.x*blockDim.x) g_hstate[i] = 0.f;
    for (int i = tid; i < BT;    i += gridDim.x*blockDim.x) g_selmap[i] = -1;
}

// ---------------- weight conversion to fp16 ------------------------------------
__global__ __launch_bounds__(256)
void cvtw_kernel(const float* __restrict__ qkvw, const float* __restrict__ projw,
                 const float* __restrict__ w1, const float* __restrict__ w2) {
    int i = blockIdx.x * 256 + threadIdx.x;
    if (i >= WTOTAL) return;
    float v;
    if (i < WOFF_PROJ)       v = qkvw[i - WOFF_QKV];
    else if (i < WOFF_FFN1)  v = projw[i - WOFF_PROJ];
    else if (i < WOFF_FFN2)  v = w1[i - WOFF_FFN1];
    else                     v = w2[i - WOFF_FFN2];
    g_wscr_h[i] = __float2half_rn(v);
}

// ---------------- split-precision conversion (x and W_ih) ----------------------
__global__ __launch_bounds__(256)
void cvtx_kernel(const float* __restrict__ x, const float* __restrict__ wih) {
    int i = blockIdx.x * 256 + threadIdx.x;
    const int NX = BT * Cn;
    const int NW = G3C * Cn;
    if (i < NX) {
        float v = x[i];
        __half hi = __float2half_rn(v);
        g_xhi[i] = hi;
        g_xlo[i] = __float2half_rn(v - __half2float(hi));
    }
    if (i < NW) {
        float v = wih[i];
        __half hi = __float2half_rn(v);
        g_wih_hi[i] = hi;
        g_wih_lo[i] = __float2half_rn(v - __half2float(hi));
    }
}

// ============================================================================
// FP16 tensor-core GEMM (mma.sync m16n8k16, cp.async 3-stage, ldmatrix frags):
// EP: 0 none, 1 gelu->half store, 2 row-scale, 3 residual, 4 plain->half store
// ============================================================================
#define GSM_BYTES 98304

template<int EP>
__global__ __launch_bounds__(256, 2)
void gemm_tc_kernel(const __half* __restrict__ A, const __half* __restrict__ W,
                    const float* __restrict__ bias, const float* __restrict__ extra,
                    float* __restrict__ Cc, int M, int N, int K) {
    extern __shared__ float smdyn[];
    uint32_t sbase = smem_u32(smdyn);
    int tid = threadIdx.x;
    int m0 = blockIdx.y * 128, n0 = blockIdx.x * 128;
    int wid = tid >> 5, L = tid & 31;
    int warp_m = wid >> 2;
    int warp_n = wid & 3;
    int r = L >> 2, c4 = L & 3;

    float cacc[4][4][4];
#pragma unroll
    for (int mt = 0; mt < 4; mt++)
#pragma unroll
        for (int nt = 0; nt < 4; nt++)
#pragma unroll
            for (int q = 0; q < 4; q++) cacc[mt][nt][q] = 0.f;

    uint32_t offA[4], offB[4];
    {
        int m_idx = L >> 3;
        uint32_t rA = (uint32_t)(warp_m*64 + (L & 15));
        uint32_t rB = (uint32_t)(warp_n*32 + (m_idx >> 1)*8 + (L & 7));
#pragma unroll
        for (int kg = 0; kg < 4; kg++) {
            offA[kg] = rA * 128 + ((((uint32_t)(2*kg + (L >> 4))) ^ (uint32_t)(L & 7)) << 4);
            offB[kg] = rB * 128 + ((((uint32_t)(2*kg + (m_idx & 1))) ^ (uint32_t)(L & 7)) << 4);
        }
    }

    auto load_tile = [&](int c, int st) {
        const __half* Ag = A + (size_t)m0 * K + c * 64;
        const __half* Wg = W + (size_t)n0 * K + c * 64;
        uint32_t ab = sbase + st * 32768;
        uint32_t wb = ab + 16384;
#pragma unroll
        for (int i = 0; i < 4; i++) {
            int idx = tid + 256 * i;
            int row = idx >> 3, g = idx & 7;
            uint32_t so = row * 128 + ((g ^ (row & 7)) << 4);
            cp16(ab + so, Ag + (size_t)row * K + g * 8);
            cp16(wb + so, Wg + (size_t)row * K + g * 8);
        }
        cp_commit();
    };

    const int NC = K >> 6;
    load_tile(0, 0);
    if (NC > 1) load_tile(1, 1);

    int st = 0, st2 = (NC > 2) ? 2 : 0;
    for (int c = 0; c < NC; c++) {
        if (c + 2 < NC) {
            load_tile(c + 2, st2);
            st2 = (st2 == 2) ? 0 : st2 + 1;
            cp_waitg<2>();
        } else if (c + 1 < NC) {
            cp_waitg<1>();
        } else {
            cp_waitg<0>();
        }
        __syncthreads();

        uint32_t Asb = sbase + st * 32768;
        uint32_t Wsb = Asb + 16384;
        st = (st == 2) ? 0 : st + 1;
#pragma unroll
        for (int kg = 0; kg < 4; kg++) {
            unsigned a[4][4];
#pragma unroll
            for (int mt = 0; mt < 4; mt++)
                ldmx4(a[mt][0], a[mt][1], a[mt][2], a[mt][3],
                      Asb + offA[kg] + mt * 2048);
            unsigned bq[4][2];
#pragma unroll
            for (int p = 0; p < 2; p++) {
                unsigned r0, r1, r2, r3;
                ldmx4(r0, r1, r2, r3, Wsb + offB[kg] + p * 2048);
                bq[2*p][0] = r0; bq[2*p][1] = r1;
                bq[2*p+1][0] = r2; bq[2*p+1][1] = r3;
            }
#pragma unroll
            for (int mt = 0; mt < 4; mt++)
#pragma unroll
                for (int nt = 0; nt < 4; nt++)
                    mma16816(cacc[mt][nt], a[mt][0], a[mt][1], a[mt][2], a[mt][3],
                             bq[nt][0], bq[nt][1]);
        }
        __syncthreads();
    }

    // ---- epilogue ----
#pragma unroll
    for (int mt = 0; mt < 4; mt++) {
        int gm = m0 + warp_m*64 + mt*16 + r;
        float rs0 = (EP == 2) ? extra[gm] : 0.f;
        float rs1 = (EP == 2) ? extra[gm + 8] : 0.f;
#pragma unroll
        for (int nt = 0; nt < 4; nt++) {
            int gn = n0 + warp_n*32 + nt*8 + 2*c4;
            float b0 = bias[gn], b1 = bias[gn + 1];
#pragma unroll
            for (int half = 0; half < 2; half++) {
                int row = gm + half*8;
                float v0 = cacc[mt][nt][half*2 + 0] + b0;
                float v1 = cacc[mt][nt][half*2 + 1] + b1;
                if (EP == 1 || EP == 4) {
                    if (EP == 1) {
                        v0 = 0.5f * v0 * (1.f + erff(v0 * 0.70710678118654752f));
                        v1 = 0.5f * v1 * (1.f + erff(v1 * 0.70710678118654752f));
                    }
                    __half* Ch = (__half*)Cc;
                    *(unsigned*)(Ch + (size_t)row * N + gn) = pkh2(v0, v1);
                    continue;
                }
                if (EP == 2) { float rs = half ? rs1 : rs0; v0 *= rs; v1 *= rs; }
                if (EP == 3) {
                    v0 += extra[(size_t)row * N + gn];
                    v1 += extra[(size_t)row * N + gn + 1];
                }
                *(float2*)(Cc + (size_t)row * N + gn) = make_float2(v0, v1);
            }
        }
    }
}

// ============================================================================
// Split-precision fp16 TC GEMM for xi (fp32-accurate), proven R12 version.
// ============================================================================
#define GSM3_BYTES 131072

__global__ __launch_bounds__(256)
void gemm_tc3_kernel(const __half* __restrict__ Ahi, const __half* __restrict__ Alo,
                     const __half* __restrict__ Whi, const __half* __restrict__ Wlo,
                     const float* __restrict__ bias, float* __restrict__ Cc,
                     int M, int N, int K) {
    extern __shared__ float smdyn[];
    uint32_t sbase = smem_u32(smdyn);
    int tid = threadIdx.x;
    int m0 = blockIdx.y * 128, n0 = blockIdx.x * 128;
    int wid = tid >> 5, L = tid & 31;
    int warp_m = wid >> 2;
    int warp_n = wid & 3;
    int r = L >> 2, c4 = L & 3;

    float cacc[4][4][4];
#pragma unroll
    for (int mt = 0; mt < 4; mt++)
#pragma unroll
        for (int nt = 0; nt < 4; nt++)
#pragma unroll
            for (int q = 0; q < 4; q++) cacc[mt][nt][q] = 0.f;

    uint32_t offA[4], offB[4];
    {
        int m_idx = L >> 3;
        uint32_t rA = (uint32_t)(warp_m*64 + (L & 15));
        uint32_t rB = (uint32_t)(warp_n*32 + (m_idx >> 1)*8 + (L & 7));
#pragma unroll
        for (int kg = 0; kg < 4; kg++) {
            offA[kg] = rA * 128 + ((((uint32_t)(2*kg + (L >> 4))) ^ (uint32_t)(L & 7)) << 4);
            offB[kg] = rB * 128 + ((((uint32_t)(2*kg + (m_idx & 1))) ^ (uint32_t)(L & 7)) << 4);
        }
    }

    auto load_tile = [&](int c, int st) {
        const __half* Ah = Ahi + (size_t)m0 * K + c * 64;
        const __half* Al = Alo + (size_t)m0 * K + c * 64;
        const __half* Wh = Whi + (size_t)n0 * K + c * 64;
        const __half* Wl = Wlo + (size_t)n0 * K + c * 64;
        uint32_t base = sbase + st * 65536;
#pragma unroll
        for (int i = 0; i < 4; i++) {
            int idx = tid + 256 * i;
            int row = idx >> 3, g = idx & 7;
            uint32_t so = row * 128 + ((g ^ (row & 7)) << 4);
            size_t go = (size_t)row * K + g * 8;
            cp16(base + so,          Ah + go);
            cp16(base + 16384 + so,  Al + go);
            cp16(base + 32768 + so,  Wh + go);
            cp16(base + 49152 + so,  Wl + go);
        }
        cp_commit();
    };

    const int NC = K >> 6;
    load_tile(0, 0);

    for (int c = 0; c < NC; c++) {
        if (c + 1 < NC) { load_tile(c + 1, (c + 1) & 1); cp_waitg<1>(); }
        else            { cp_waitg<0>(); }
        __syncthreads();

        uint32_t Sb = sbase + (c & 1) * 65536;
#pragma unroll
        for (int kg = 0; kg < 4; kg++) {
            unsigned ah[4][4], al[4][4];
#pragma unroll
            for (int mt = 0; mt < 4; mt++) {
                ldmx4(ah[mt][0], ah[mt][1], ah[mt][2], ah[mt][3],
                      Sb + offA[kg] + mt * 2048);
                ldmx4(al[mt][0], al[mt][1], al[mt][2], al[mt][3],
                      Sb + 16384 + offA[kg] + mt * 2048);
            }
            unsigned bh[4][2], bl[4][2];
#pragma unroll
            for (int p = 0; p < 2; p++) {
                unsigned r0, r1, r2, r3;
                ldmx4(r0, r1, r2, r3, Sb + 32768 + offB[kg] + p * 2048);
                bh[2*p][0] = r0; bh[2*p][1] = r1;
                bh[2*p+1][0] = r2; bh[2*p+1][1] = r3;
                ldmx4(r0, r1, r2, r3, Sb + 49152 + offB[kg] + p * 2048);
                bl[2*p][0] = r0; bl[2*p][1] = r1;
                bl[2*p+1][0] = r2; bl[2*p+1][1] = r3;
            }
#pragma unroll
            for (int mt = 0; mt < 4; mt++)
#pragma unroll
                for (int nt = 0; nt < 4; nt++) {
                    mma16816(cacc[mt][nt], ah[mt][0], ah[mt][1], ah[mt][2], ah[mt][3],
                             bh[nt][0], bh[nt][1]);
                    mma16816(cacc[mt][nt], ah[mt][0], ah[mt][1], ah[mt][2], ah[mt][3],
                             bl[nt][0], bl[nt][1]);
                    mma16816(cacc[mt][nt], al[mt][0], al[mt][1], al[mt][2], al[mt][3],
                             bh[nt][0], bh[nt][1]);
                }
        }
        __syncthreads();
    }

#pragma unroll
    for (int mt = 0; mt < 4; mt++) {
        int gm = m0 + warp_m*64 + mt*16 + r;
#pragma unroll
        for (int nt = 0; nt < 4; nt++) {
            int gn = n0 + warp_n*32 + nt*8 + 2*c4;
            float b0 = bias[gn], b1 = bias[gn + 1];
#pragma unroll
            for (int half = 0; half < 2; half++) {
                int row = gm + half*8;
                *(float2*)(Cc + (size_t)row * N + gn) =
                    make_float2(cacc[mt][nt][half*2] + b0, cacc[mt][nt][half*2+1] + b1);
            }
        }
    }
}

// ---------------- GRU persistent kernel (2 groups; release/acquire sync) ------
#define GRP_CTAS 64
#define CHB 12
__global__ __launch_bounds__(384, 1)
void gru_kernel(const float* __restrict__ xi, const float* __restrict__ Whh,
                const float* __restrict__ bhh) {
    __shared__ float hs[4][Cn];
    __shared__ float gbuf[CHB][3][4];
    int tid = threadIdx.x, w = tid >> 5, lane = tid & 31;
    int grp = blockIdx.x >> 6;          // 0..1
    int cb  = blockIdx.x & 63;
    int c0 = cb * CHB;
    int ch = c0 + w;                    // warp's channel
    int b0 = grp * 4;                   // group's batch base

    ull wp[3][6][2];
#pragma unroll
    for (int g = 0; g < 3; g++)
#pragma unroll
        for (int j = 0; j < 6; j++) {
            float4 v = __ldg((const float4*)(Whh + (size_t)(g*Cn + ch) * Cn) + (j*32 + lane));
            wp[g][j][0] = pk2(v.x, v.y);
            wp[g][j][1] = pk2(v.z, v.w);
        }

    bool is_comb = tid < (4 * CHB);     // 48 combiner threads
    int bcl = 0, ccomb = 0;
    float bhr = 0.f, bhz = 0.f, bhn = 0.f;
    const float* xrow0 = xi;
    if (is_comb) {
        bcl = tid / CHB;                // 0..3 local batch
        ccomb = c0 + tid % CHB;
        bhr = __ldg(bhh + ccomb);
        bhz = __ldg(bhh + Cn + ccomb);
        bhn = __ldg(bhh + 2*Cn + ccomb);
        xrow0 = xi + (size_t)(b0 + bcl) * Tn * G3C + ccomb;
    }
    int gb = b0 + bcl;                  // global batch (comb threads)

    unsigned* bar = &g_bars[grp * 32];
    unsigned target = GRP_CTAS;
    for (int t = 0; t < Tn; t++) {
        // stage group's h slice: 4 x 768 floats = 768 float4
        const float4* hp = (const float4*)(g_hstate + b0 * Cn);
        float4* hd = (float4*)&hs[0][0];
        hd[tid]       = __ldcg(hp + tid);
        hd[tid + 384] = __ldcg(hp + tid + 384);

        float xr = 0.f, xz = 0.f, xn = 0.f;
        if (is_comb) {
            const float* xrow = xrow0 + (size_t)t * G3C;
            xr = __ldg(xrow); xz = __ldg(xrow + Cn); xn = __ldg(xrow + 2*Cn);
        }
        __syncthreads();

        ull acc2[3][4];
#pragma unroll
        for (int g = 0; g < 3; g++)
#pragma unroll
            for (int b = 0; b < 4; b++) acc2[g][b] = 0ull;

#pragma unroll
        for (int j = 0; j < 6; j++) {
            ull h01[4], h23[4];
#pragma unroll
            for (int b = 0; b < 4; b++) {
                float4 h4 = ((const float4*)&hs[b][0])[j*32 + lane];
                h01[b] = pk2(h4.x, h4.y);
                h23[b] = pk2(h4.z, h4.w);
            }
#pragma unroll
            for (int b = 0; b < 4; b++)
#pragma unroll
                for (int g = 0; g < 3; g++) {
                    fma2(acc2[g][b], wp[g][j][0], h01[b]);
                    fma2(acc2[g][b], wp[g][j][1], h23[b]);
                }
        }
#pragma unroll
        for (int g = 0; g < 3; g++)
#pragma unroll
            for (int b = 0; b < 4; b++) {
                float2 p = upk2(acc2[g][b]);
                float v = p.x + p.y;
#pragma unroll
                for (int off = 16; off > 0; off >>= 1)
                    v += __shfl_xor_sync(0xffffffffu, v, off);
                if (lane == 0) gbuf[w][g][b] = v;
            }
        __syncthreads();

        if (is_comb) {
            int cc = tid % CHB;
            float hr = gbuf[cc][0][bcl] + bhr;
            float hz = gbuf[cc][1][bcl] + bhz;
            float hn = gbuf[cc][2][bcl] + bhn;
            float r = 1.f / (1.f + expf(-(xr + hr)));
            float z = 1.f / (1.f + expf(-(xz + hz)));
            float n = tanhf(xn + r * hn);
            float hold = hs[bcl][ccomb];
            float hnew = (1.f - z) * n + z * hold;
            g_hstate[gb*Cn + ccomb] = hnew;
            g_hrnn[((size_t)gb*Tn + t) * Cn + ccomb] = hnew;
        }
        __syncthreads();
        if (tid == 0) {
            red_release_add(bar, 1u);                  // release: prior stores visible
            while (ld_acquire(bar) < target) { }       // tight acquire poll
        }
        target += GRP_CTAS;
        __syncthreads();
    }
}

// ---------------- gate MLP / energy -------------------------------------------
__global__ __launch_bounds__(128)
void energy_kernel(const float* __restrict__ gw1, const float* __restrict__ gb1,
                   const float* __restrict__ gw2, const float* __restrict__ gb2,
                   float* __restrict__ out_energy) {
    int tok = blockIdx.x;
    int tid = threadIdx.x, w = tid >> 5, lane = tid & 31;
    __shared__ float dots[32];
    const float* h = g_hrnn + (size_t)tok * Cn;
#pragma unroll
    for (int jj = 0; jj < 8; jj++) {
        int j = w * 8 + jj;
        const float* wr = gw1 + (size_t)j * Cn;
        float p = 0.f;
        for (int k = lane; k < Cn; k += 32) p += h[k] * wr[k];
#pragma unroll
        for (int off = 16; off > 0; off >>= 1) p += __shfl_xor_sync(0xffffffffu, p, off);
        if (lane == 0) dots[j] = p;
    }
    __syncthreads();
    if (tid == 0) {
        float a = gb2[0];
#pragma unroll
        for (int j = 0; j < 32; j++) a += tanhf(dots[j] + gb1[j]) * gw2[j];
        float e = 1.f / (1.f + expf(-a));
        g_energy[tok] = e;
        out_energy[tok] = e;
        if (e > 0.5f) atomicAdd(&g_active, 1);
    }
}

// ---------------- exact top-k via bitonic sort ---------------------------------
__global__ __launch_bounds__(1024)
void topk_kernel() {
    __shared__ unsigned long long keys[Tn];
    __shared__ int sel[KSEL];
    int b = blockIdx.x, tid = threadIdx.x;
    for (int e = tid; e < Tn; e += 1024) {
        unsigned u = __float_as_uint(g_energy[b*Tn + e]);
        u = (u & 0x80000000u) ? ~u : (u | 0x80000000u);
        keys[e] = ((unsigned long long)u << 32) | (unsigned)(Tn - 1 - e);
    }
    __syncthreads();
    for (int k = 2; k <= Tn; k <<= 1)
        for (int j = k >> 1; j > 0; j >>= 1) {
            int p = tid;
            int e = ((p & ~(j - 1)) << 1) | (p & (j - 1));
            int f = e | j;
            unsigned long long a = keys[e], c = keys[f];
            bool up = ((e & k) == 0);
            bool sw = up ? (a < c) : (a > c);
            if (sw) { keys[e] = c; keys[f] = a; }
            __syncthreads();
        }
    if (tid < KSEL) sel[tid] = Tn - 1 - (int)(keys[tid] & 0xffffffffull);
    __syncthreads();
    for (int k = 2; k <= KSEL; k <<= 1)
        for (int j = k >> 1; j > 0; j >>= 1) {
            if (tid < KSEL/2) {
                int p = tid;
                int e = ((p & ~(j - 1)) << 1) | (p & (j - 1));
                int f = e | j;
                int a = sel[e], c = sel[f];
                bool up = ((e & k) == 0);
                bool sw = up ? (a > c) : (a < c);
                if (sw) { sel[e] = c; sel[f] = a; }
            }
            __syncthreads();
        }
    if (tid < KSEL) g_idx[b*KSEL + tid] = sel[tid];
}

// ---------------- gather selected tokens (store fp16) ---------------------------
__global__ __launch_bounds__(192)
void gather_kernel() {
    int bk = blockIdx.x;
    int b = bk / KSEL;
    int t = g_idx[bk];
    if (threadIdx.x == 0) {
        g_gsel[bk] = g_energy[b*Tn + t];
        g_selmap[b*Tn + t] = bk % KSEL;
    }
    float4 v = ((const float4*)(g_hrnn + ((size_t)b*Tn + t) * Cn))[threadIdx.x];
    uint2 o = make_uint2(pkh2(v.x, v.y), pkh2(v.z, v.w));
    *(uint2*)(g_xsel_h + (size_t)bk * Cn + threadIdx.x * 4) = o;
}

// ============================================================================
// Flash attention, fp16 tensor cores (proven R10 version).
// ============================================================================
#define ASTB 144
#define ATT_TILE_B (64*ASTB)
#define ATT_STAGE  (2*ATT_TILE_B)
#define ATT_SMEM   (2*ATT_STAGE)

__global__ __launch_bounds__(128)
void attn_kernel() {
    extern __shared__ char smc[];
    uint32_t sb = smem_u32(smc);
    int qt = blockIdx.x, bh = blockIdx.y;
    int b = bh / Hn, h = bh % Hn;
    int tid = threadIdx.x, w = tid >> 5, l = tid & 31;
    int g = l >> 2, c = l & 3;
    int q0 = qt * 64;
    const __half* qkv = g_qkv_h + (size_t)b * KSEL * G3C;

    unsigned qw[2][8];
    {
        const unsigned* qlo = (const unsigned*)(qkv + (size_t)(q0 + w*16 + g) * G3C + h*64);
        const unsigned* qhi = (const unsigned*)(qkv + (size_t)(q0 + w*16 + g + 8) * G3C + h*64);
#pragma unroll
        for (int j = 0; j < 8; j++) { qw[0][j] = qlo[4*j + c]; qw[1][j] = qhi[4*j + c]; }
    }

    auto load_kv = [&](int kt, int st) {
        int row = tid >> 1;
        int q = (tid & 1) * 4;
        const __half* Kg = qkv + (size_t)(kt*64 + row) * G3C + Cn + h*64;
        const __half* Vg = qkv + (size_t)(kt*64 + row) * G3C + 2*Cn + h*64;
        uint32_t kb = sb + st*ATT_STAGE + row*ASTB;
        uint32_t vb = kb + ATT_TILE_B;
#pragma unroll
        for (int e = 0; e < 4; e++) {
            cp16(kb + (q+e)*16, Kg + (q+e)*8);
            cp16(vb + (q+e)*16, Vg + (q+e)*8);
        }
        cp_commit();
    };

    float O[8][4];
#pragma unroll
    for (int nt = 0; nt < 8; nt++)
#pragma unroll
        for (int q = 0; q < 4; q++) O[nt][q] = 0.f;
    float m_lo = -1e30f, m_hi = -1e30f, l_lo = 0.f, l_hi = 0.f;

    load_kv(0, 0);

    for (int kt = 0; kt <= qt; kt++) {
        if (kt < qt) { load_kv(kt + 1, (kt + 1) & 1); cp_waitg<1>(); }
        else         { cp_waitg<0>(); }
        __syncthreads();

        uint32_t Ks = sb + (kt & 1) * ATT_STAGE;
        uint32_t Vs = Ks + ATT_TILE_B;

        float s[8][4];
#pragma unroll
        for (int nt = 0; nt < 8; nt++)
#pragma unroll
            for (int q = 0; q < 4; q++) s[nt][q] = 0.f;
#pragma unroll
        for (int kg = 0; kg < 4; kg++) {
            unsigned a0 = qw[0][2*kg], a1 = qw[1][2*kg];
            unsigned a2 = qw[0][2*kg+1], a3 = qw[1][2*kg+1];
#pragma unroll
            for (int np = 0; np < 4; np++) {
                unsigned k0, k1, k2, k3;
                uint32_t addr = Ks + (16*np + ((l & 16) ? 8 : 0) + (l & 7)) * ASTB
                                   + (16*kg + ((l & 8) ? 8 : 0)) * 2;
                ldmx4(k0, k1, k2, k3, addr);
                mma16816(s[2*np],     a0, a1, a2, a3, k0, k1);
                mma16816(s[2*np + 1], a0, a1, a2, a3, k2, k3);
            }
        }
#pragma unroll
        for (int nt = 0; nt < 8; nt++)
#pragma unroll
            for (int q = 0; q < 4; q++) s[nt][q] *= 0.125f;
        if (kt == qt) {
#pragma unroll
            for (int nt = 0; nt < 8; nt++)
#pragma unroll
                for (int e = 0; e < 2; e++) {
                    int col = 8*nt + 2*c + e;
                    if (col > 16*w + g)     s[nt][e]     = -1e30f;
                    if (col > 16*w + g + 8) s[nt][2 + e] = -1e30f;
                }
        }
        float rm_lo = -1e30f, rm_hi = -1e30f;
#pragma unroll
        for (int nt = 0; nt < 8; nt++) {
            rm_lo = fmaxf(rm_lo, fmaxf(s[nt][0], s[nt][1]));
            rm_hi = fmaxf(rm_hi, fmaxf(s[nt][2], s[nt][3]));
        }
#pragma unroll
        for (int off = 1; off <= 2; off <<= 1) {
            rm_lo = fmaxf(rm_lo, __shfl_xor_sync(0xffffffffu, rm_lo, off));
            rm_hi = fmaxf(rm_hi, __shfl_xor_sync(0xffffffffu, rm_hi, off));
        }
        float mn_lo = fmaxf(m_lo, rm_lo), mn_hi = fmaxf(m_hi, rm_hi);
        float al_lo = expf(m_lo - mn_lo), al_hi = expf(m_hi - mn_hi);
        m_lo = mn_lo; m_hi = mn_hi;
        float rs_lo = 0.f, rs_hi = 0.f;
#pragma unroll
        for (int nt = 0; nt < 8; nt++) {
            s[nt][0] = expf(s[nt][0] - mn_lo);
            s[nt][1] = expf(s[nt][1] - mn_lo);
            s[nt][2] = expf(s[nt][2] - mn_hi);
            s[nt][3] = expf(s[nt][3] - mn_hi);
            rs_lo += s[nt][0] + s[nt][1];
            rs_hi += s[nt][2] + s[nt][3];
        }
#pragma unroll
        for (int off = 1; off <= 2; off <<= 1) {
            rs_lo += __shfl_xor_sync(0xffffffffu, rs_lo, off);
            rs_hi += __shfl_xor_sync(0xffffffffu, rs_hi, off);
        }
        l_lo = l_lo * al_lo + rs_lo;
        l_hi = l_hi * al_hi + rs_hi;
#pragma unroll
        for (int nt = 0; nt < 8; nt++) {
            O[nt][0] *= al_lo; O[nt][1] *= al_lo;
            O[nt][2] *= al_hi; O[nt][3] *= al_hi;
        }
        unsigned pa[4][4];
#pragma unroll
        for (int kg = 0; kg < 4; kg++) {
            pa[kg][0] = pkh2(s[2*kg][0],     s[2*kg][1]);
            pa[kg][1] = pkh2(s[2*kg][2],     s[2*kg][3]);
            pa[kg][2] = pkh2(s[2*kg+1][0],   s[2*kg+1][1]);
            pa[kg][3] = pkh2(s[2*kg+1][2],   s[2*kg+1][3]);
        }
#pragma unroll
        for (int kg = 0; kg < 4; kg++) {
#pragma unroll
            for (int np = 0; np < 4; np++) {
                unsigned v0, v1, v2, v3;
                uint32_t addr = Vs + (16*kg + ((l & 8) ? 8 : 0) + (l & 7)) * ASTB
                                   + (16*np + ((l & 16) ? 8 : 0)) * 2;
                ldmx4t(v0, v1, v2, v3, addr);
                mma16816(O[2*np],     pa[kg][0], pa[kg][1], pa[kg][2], pa[kg][3], v0, v1);
                mma16816(O[2*np + 1], pa[kg][0], pa[kg][1], pa[kg][2], pa[kg][3], v2, v3);
            }
        }
        __syncthreads();
    }

    float inv_lo = 1.f / l_lo, inv_hi = 1.f / l_hi;
    int rlo = b * KSEL + q0 + w*16 + g;
#pragma unroll
    for (int nt = 0; nt < 8; nt++) {
        int col = h*64 + 8*nt + 2*c;
        *(unsigned*)(g_y_h + (size_t)rlo * Cn + col) =
            pkh2(O[nt][0] * inv_lo, O[nt][1] * inv_lo);
        *(unsigned*)(g_y_h + (size_t)(rlo + 8) * Cn + col) =
            pkh2(O[nt][2] * inv_hi, O[nt][3] * inv_hi);
    }
}

// ---------------- LayerNorm (fp32 hln + fp16 copy) ------------------------------
__global__ __launch_bounds__(256)
void ln_kernel(const float* __restrict__ g, const float* __restrict__ bb,
               __half* __restrict__ hlnr) {
    __shared__ float xrow[Cn];
    __shared__ float rbuf[16];
    int tok = blockIdx.x, tid = threadIdx.x;
    int b = tok >> 11;
    int sel = g_selmap[tok];
    float s = 0.f, s2 = 0.f;
    for (int c = tid; c < Cn; c += 256) {
        float v = g_hrnn[(size_t)tok*Cn + c];
        if (sel >= 0) v += g_weighted[((size_t)(b*KSEL + sel))*Cn + c];
        xrow[c] = v; s += v; s2 += v*v;
    }
#pragma unroll
    for (int off = 16; off > 0; off >>= 1) {
        s  += __shfl_xor_sync(0xffffffffu, s, off);
        s2 += __shfl_xor_sync(0xffffffffu, s2, off);
    }
    int w = tid >> 5;
    if ((tid & 31) == 0) { rbuf[w] = s; rbuf[8 + w] = s2; }
    __syncthreads();
    if (tid == 0) {
        float S = 0.f, S2 = 0.f;
        for (int i = 0; i < 8; i++) { S += rbuf[i]; S2 += rbuf[8 + i]; }
        float mu = S / (float)Cn;
        float var = S2 / (float)Cn - mu*mu;
        rbuf[0] = mu; rbuf[1] = rsqrtf(var + 1e-5f);
    }
    __syncthreads();
    float mu = rbuf[0], inv = rbuf[1];
    for (int c = tid; c < Cn; c += 256) {
        float v = (xrow[c] - mu) * inv * g[c] + bb[c];
        g_hln[(size_t)tok*Cn + c] = v;
        hlnr[(size_t)tok*Cn + c] = __float2half_rn(v);
    }
}

// ---------------- finalize ------------------------------------------------------
__global__ void finalize_kernel(float* out) {
    out[(size_t)BT*Cn + BT] = (float)g_active;
}

// ---------------- launcher ------------------------------------------------------
extern "C" void kernel_launch(void* const* d_in, const int* in_sizes, int n_in,
                              void* d_out, int out_size) {
    const float* x      = (const float*)d_in[0];
    const float* W_ih   = (const float*)d_in[1];
    const float* W_hh   = (const float*)d_in[2];
    const float* b_ih   = (const float*)d_in[3];
    const float* b_hh   = (const float*)d_in[4];
    const float* gate_w1= (const float*)d_in[5];
    const float* gate_b1= (const float*)d_in[6];
    const float* gate_w2= (const float*)d_in[7];
    const float* gate_b2= (const float*)d_in[8];
    const float* qkv_w  = (const float*)d_in[9];
    const float* qkv_b  = (const float*)d_in[10];
    const float* proj_w = (const float*)d_in[11];
    const float* proj_b = (const float*)d_in[12];
    const float* ln_g   = (const float*)d_in[13];
    const float* ln_b   = (const float*)d_in[14];
    const float* ffn_w1 = (const float*)d_in[15];
    const float* ffn_b1 = (const float*)d_in[16];
    const float* ffn_w2 = (const float*)d_in[17];
    const float* ffn_b2 = (const float*)d_in[18];
    float* out = (float*)d_out;

    float *p_xi, *p_weighted, *p_hln;
    __half *p_xsel, *p_qkvh, *p_y, *p_mid, *p_wscr, *p_xhi, *p_xlo, *p_whi, *p_wlo;
    cudaGetSymbolAddress((void**)&p_xi,       g_xi);
    cudaGetSymbolAddress((void**)&p_xsel,     g_xsel_h);
    cudaGetSymbolAddress((void**)&p_qkvh,     g_qkv_h);
    cudaGetSymbolAddress((void**)&p_y,        g_y_h);
    cudaGetSymbolAddress((void**)&p_weighted, g_weighted);
    cudaGetSymbolAddress((void**)&p_hln,      g_hln);
    cudaGetSymbolAddress((void**)&p_mid,      g_mid_h);
    cudaGetSymbolAddress((void**)&p_wscr,     g_wscr_h);
    cudaGetSymbolAddress((void**)&p_xhi,      g_xhi);
    cudaGetSymbolAddress((void**)&p_xlo,      g_xlo);
    cudaGetSymbolAddress((void**)&p_whi,      g_wih_hi);
    cudaGetSymbolAddress((void**)&p_wlo,      g_wih_lo);
    float* p_gsel; cudaGetSymbolAddress((void**)&p_gsel, g_gsel);
    float* p_energy_out = out + (size_t)BT*Cn;
    __half* p_hlnr = (__half*)p_xi;

    cudaFuncSetAttribute(attn_kernel, cudaFuncAttributeMaxDynamicSharedMemorySize, ATT_SMEM);
    cudaFuncSetAttribute(gemm_tc_kernel<1>, cudaFuncAttributeMaxDynamicSharedMemorySize, GSM_BYTES);
    cudaFuncSetAttribute(gemm_tc_kernel<2>, cudaFuncAttributeMaxDynamicSharedMemorySize, GSM_BYTES);
    cudaFuncSetAttribute(gemm_tc_kernel<3>, cudaFuncAttributeMaxDynamicSharedMemorySize, GSM_BYTES);
    cudaFuncSetAttribute(gemm_tc_kernel<4>, cudaFuncAttributeMaxDynamicSharedMemorySize, GSM_BYTES);
    cudaFuncSetAttribute(gemm_tc3_kernel,   cudaFuncAttributeMaxDynamicSharedMemorySize, GSM3_BYTES);

    // 0) init
    init_kernel<<<64, 256>>>();

    // 1) weights -> fp16; x/W_ih -> split fp16
    cvtw_kernel<<<(WTOTAL + 255)/256, 256>>>(qkv_w, proj_w, ffn_w1, ffn_w2);
    cvtx_kernel<<<(BT*Cn + 255)/256, 256>>>(x, W_ih);

    // 2) xi = x @ W_ih^T + b_ih  (split-precision fp16 TC, fp32-accurate)
    gemm_tc3_kernel<<<dim3(G3C/128, BT/128), 256, GSM3_BYTES>>>(
        p_xhi, p_xlo, p_whi, p_wlo, b_ih, p_xi, BT, G3C, Cn);

    // 3) GRU scan (2 independent batch groups x 64 CTAs, release/acquire sync)
    gru_kernel<<<2*GRP_CTAS, 384>>>(p_xi, W_hh, b_hh);

    // 4) energy
    energy_kernel<<<BT, 128>>>(gate_w1, gate_b1, gate_w2, gate_b2, p_energy_out);

    // 5) top-k
    topk_kernel<<<Bn, 1024>>>();

    // 6) gather (fp16 xsel)
    gather_kernel<<<BKn, 192>>>();

    // 7) qkv GEMM (fp16 in, fp16 out)
    gemm_tc_kernel<4><<<dim3(G3C/128, BKn/128), 256, GSM_BYTES>>>(
        p_xsel, p_wscr + WOFF_QKV, qkv_b, nullptr, (float*)p_qkvh, BKn, G3C, Cn);

    // 8) attention (tensor-core flash, fp16 y)
    attn_kernel<<<dim3(KSEL/64, Bn*Hn), 128, ATT_SMEM>>>();

    // 9) proj GEMM (row-scale)
    gemm_tc_kernel<2><<<dim3(Cn/128, BKn/128), 256, GSM_BYTES>>>(
        p_y, p_wscr + WOFF_PROJ, proj_b, p_gsel, p_weighted, BKn, Cn, Cn);

    // 10) LayerNorm
    ln_kernel<<<BT, 256>>>(ln_g, ln_b, p_hlnr);

    // 11) ffn1 GEMM (gelu -> fp16 mid)
    gemm_tc_kernel<1><<<dim3(DFF/128, BT/128), 256, GSM_BYTES>>>(
        (const __half*)p_hlnr, p_wscr + WOFF_FFN1, ffn_b1, nullptr, (float*)p_mid, BT, DFF, Cn);

    // 12) ffn2 GEMM (residual) -> out
    gemm_tc_kernel<3><<<dim3(Cn/128, BT/128), 256, GSM_BYTES>>>(
        p_mid, p_wscr + WOFF_FFN2, ffn_b2, p_hln, out, BT, Cn, DFF);

    // 13) active count
    finalize_kernel<<<1, 1>>>(out);

    (void)in_sizes; (void)n_in; (void)out_size;
}

// round 16
// speedup vs baseline: 1.0081x; 1.0081x over previous
#include <cuda_runtime.h>
#include <cuda_fp16.h>
#include <math.h>
#include <stdint.h>

#define Bn 8
#define Tn 2048
#define Cn 768
#define Hn 12
#define KSEL 1024
#define DFF 3072
#define BT (Bn*Tn)      /* 16384 */
#define BKn (Bn*KSEL)   /* 8192 */
#define G3C (3*Cn)      /* 2304 */

typedef unsigned long long ull;

// ---------------- f32x2 packed helpers --------------------------------------
__device__ __forceinline__ ull pk2(float x, float y) {
    ull r; asm("mov.b64 %0, {%1, %2};" : "=l"(r) : "f"(x), "f"(y)); return r;
}
__device__ __forceinline__ void fma2(ull &acc, ull a, ull b) {
    asm("fma.rn.f32x2 %0, %1, %2, %0;" : "+l"(acc) : "l"(a), "l"(b));
}
__device__ __forceinline__ float2 upk2(ull v) {
    float2 r; asm("mov.b64 {%0, %1}, %2;" : "=f"(r.x), "=f"(r.y) : "l"(v)); return r;
}
__device__ __forceinline__ unsigned pkh2(float a, float b) {
    __half2 h = __floats2half2_rn(a, b);
    return *reinterpret_cast<unsigned*>(&h);
}

// ---------------- cp.async / smem helpers ------------------------------------
__device__ __forceinline__ uint32_t smem_u32(const void* p) {
    uint32_t a; asm("{ .reg .u64 t; cvta.to.shared.u64 t, %1; cvt.u32.u64 %0, t; }"
                    : "=r"(a) : "l"(p));
    return a;
}
__device__ __forceinline__ void cp16(uint32_t saddr, const void* gaddr) {
    asm volatile("cp.async.cg.shared.global [%0], [%1], 16;"
                 :: "r"(saddr), "l"(__cvta_generic_to_global(gaddr)));
}
__device__ __forceinline__ void cp_commit() { asm volatile("cp.async.commit_group;"); }
template<int N>
__device__ __forceinline__ void cp_waitg() {
    asm volatile("cp.async.wait_group %0;" :: "n"(N) : "memory");
}
__device__ __forceinline__ void ldmx4(unsigned &r0, unsigned &r1, unsigned &r2,
                                      unsigned &r3, uint32_t addr) {
    asm volatile("ldmatrix.sync.aligned.m8n8.x4.shared.b16 {%0,%1,%2,%3}, [%4];"
                 : "=r"(r0), "=r"(r1), "=r"(r2), "=r"(r3) : "r"(addr));
}
__device__ __forceinline__ void ldmx4t(unsigned &r0, unsigned &r1, unsigned &r2,
                                       unsigned &r3, uint32_t addr) {
    asm volatile("ldmatrix.sync.aligned.m8n8.x4.trans.shared.b16 {%0,%1,%2,%3}, [%4];"
                 : "=r"(r0), "=r"(r1), "=r"(r2), "=r"(r3) : "r"(addr));
}
__device__ __forceinline__ void mma16816(float* d, unsigned a0, unsigned a1,
                                         unsigned a2, unsigned a3,
                                         unsigned b0, unsigned b1) {
    asm volatile("mma.sync.aligned.m16n8k16.row.col.f32.f16.f16.f32 "
                 "{%0,%1,%2,%3}, {%4,%5,%6,%7}, {%8,%9}, {%0,%1,%2,%3};"
                 : "+f"(d[0]), "+f"(d[1]), "+f"(d[2]), "+f"(d[3])
                 : "r"(a0), "r"(a1), "r"(a2), "r"(a3), "r"(b0), "r"(b1));
}
// release-reduce arrival + acquire poll (GPU scope)
__device__ __forceinline__ void red_release_add(unsigned* addr, unsigned v) {
    asm volatile("red.release.gpu.global.add.u32 [%0], %1;"
                 :: "l"(addr), "r"(v) : "memory");
}
__device__ __forceinline__ unsigned ld_acquire(const unsigned* addr) {
    unsigned v;
    asm volatile("ld.acquire.gpu.global.u32 %0, [%1];" : "=r"(v) : "l"(addr) : "memory");
    return v;
}

// ---------------- scratch -----------------------------------------------------
__device__ float g_xi[(size_t)BT*G3C];     // xi; later reused as half hlnr
__device__ float g_hrnn[(size_t)BT*Cn];
__device__ float g_hstate[Bn*Cn];
__device__ float g_energy[BT];
__device__ int   g_idx[BKn];
__device__ int   g_selmap[BT];
__device__ __half g_xsel_h[(size_t)BKn*Cn];
__device__ float g_gsel[BKn];
__device__ __half g_qkv_h[(size_t)BKn*G3C];
__device__ __half g_y_h[(size_t)BKn*Cn];
__device__ float g_weighted[(size_t)BKn*Cn];
__device__ float g_hln[(size_t)BT*Cn];
__device__ __half g_mid_h[(size_t)BT*DFF];
__device__ __half g_wscr_h[7077888];       // half weights: qkv|proj|ffn1|ffn2
__device__ __half g_xhi[(size_t)BT*Cn];
__device__ __half g_xlo[(size_t)BT*Cn];
__device__ __half g_wih_hi[(size_t)G3C*Cn];
__device__ __half g_wih_lo[(size_t)G3C*Cn];
__device__ unsigned g_bars[64];            // 2 group barriers, 128B apart
__device__ int g_active;

#define WOFF_QKV  0
#define WOFF_PROJ 1769472
#define WOFF_FFN1 2359296
#define WOFF_FFN2 4718592
#define WTOTAL    7077888

// ---------------- init --------------------------------------------------------
__global__ void init_kernel() {
    int tid = blockIdx.x * blockDim.x + threadIdx.x;
    if (tid == 0) g_active = 0;
    if (tid < 64) g_bars[tid] = 0u;
    for (int i = tid; i < Bn*Cn; i += gridDim.x*blockDim.x) g_hstate[i] = 0.f;
    for (int i = tid; i < BT;    i += gridDim.x*blockDim.x) g_selmap[i] = -1;
}

// ---------------- weight conversion to fp16 ------------------------------------
__global__ __launch_bounds__(256)
void cvtw_kernel(const float* __restrict__ qkvw, const float* __restrict__ projw,
                 const float* __restrict__ w1, const float* __restrict__ w2) {
    int i = blockIdx.x * 256 + threadIdx.x;
    if (i >= WTOTAL) return;
    float v;
    if (i < WOFF_PROJ)       v = qkvw[i - WOFF_QKV];
    else if (i < WOFF_FFN1)  v = projw[i - WOFF_PROJ];
    else if (i < WOFF_FFN2)  v = w1[i - WOFF_FFN1];
    else                     v = w2[i - WOFF_FFN2];
    g_wscr_h[i] = __float2half_rn(v);
}

// ---------------- split-precision conversion (x and W_ih) ----------------------
__global__ __launch_bounds__(256)
void cvtx_kernel(const float* __restrict__ x, const float* __restrict__ wih) {
    int i = blockIdx.x * 256 + threadIdx.x;
    const int NX = BT * Cn;
    const int NW = G3C * Cn;
    if (i < NX) {
        float v = x[i];
        __half hi = __float2half_rn(v);
        g_xhi[i] = hi;
        g_xlo[i] = __float2half_rn(v - __half2float(hi));
    }
    if (i < NW) {
        float v = wih[i];
        __half hi = __float2half_rn(v);
        g_wih_hi[i] = hi;
        g_wih_lo[i] = __float2half_rn(v - __half2float(hi));
    }
}

// ============================================================================
// FP16 tensor-core GEMM (mma.sync m16n8k16, cp.async 3-stage, ldmatrix frags):
// EP: 0 none, 1 gelu->half store, 2 row-scale, 3 residual, 4 plain->half store
// ============================================================================
#define GSM_BYTES 98304

template<int EP>
__global__ __launch_bounds__(256, 2)
void gemm_tc_kernel(const __half* __restrict__ A, const __half* __restrict__ W,
                    const float* __restrict__ bias, const float* __restrict__ extra,
                    float* __restrict__ Cc, int M, int N, int K) {
    extern __shared__ float smdyn[];
    uint32_t sbase = smem_u32(smdyn);
    int tid = threadIdx.x;
    int m0 = blockIdx.y * 128, n0 = blockIdx.x * 128;
    int wid = tid >> 5, L = tid & 31;
    int warp_m = wid >> 2;
    int warp_n = wid & 3;
    int r = L >> 2, c4 = L & 3;

    float cacc[4][4][4];
#pragma unroll
    for (int mt = 0; mt < 4; mt++)
#pragma unroll
        for (int nt = 0; nt < 4; nt++)
#pragma unroll
            for (int q = 0; q < 4; q++) cacc[mt][nt][q] = 0.f;

    uint32_t offA[4], offB[4];
    {
        int m_idx = L >> 3;
        uint32_t rA = (uint32_t)(warp_m*64 + (L & 15));
        uint32_t rB = (uint32_t)(warp_n*32 + (m_idx >> 1)*8 + (L & 7));
#pragma unroll
        for (int kg = 0; kg < 4; kg++) {
            offA[kg] = rA * 128 + ((((uint32_t)(2*kg + (L >> 4))) ^ (uint32_t)(L & 7)) << 4);
            offB[kg] = rB * 128 + ((((uint32_t)(2*kg + (m_idx & 1))) ^ (uint32_t)(L & 7)) << 4);
        }
    }

    auto load_tile = [&](int c, int st) {
        const __half* Ag = A + (size_t)m0 * K + c * 64;
        const __half* Wg = W + (size_t)n0 * K + c * 64;
        uint32_t ab = sbase + st * 32768;
        uint32_t wb = ab + 16384;
#pragma unroll
        for (int i = 0; i < 4; i++) {
            int idx = tid + 256 * i;
            int row = idx >> 3, g = idx & 7;
            uint32_t so = row * 128 + ((g ^ (row & 7)) << 4);
            cp16(ab + so, Ag + (size_t)row * K + g * 8);
            cp16(wb + so, Wg + (size_t)row * K + g * 8);
        }
        cp_commit();
    };

    const int NC = K >> 6;
    load_tile(0, 0);
    if (NC > 1) load_tile(1, 1);

    int st = 0, st2 = (NC > 2) ? 2 : 0;
    for (int c = 0; c < NC; c++) {
        if (c + 2 < NC) {
            load_tile(c + 2, st2);
            st2 = (st2 == 2) ? 0 : st2 + 1;
            cp_waitg<2>();
        } else if (c + 1 < NC) {
            cp_waitg<1>();
        } else {
            cp_waitg<0>();
        }
        __syncthreads();

        uint32_t Asb = sbase + st * 32768;
        uint32_t Wsb = Asb + 16384;
        st = (st == 2) ? 0 : st + 1;
#pragma unroll
        for (int kg = 0; kg < 4; kg++) {
            unsigned a[4][4];
#pragma unroll
            for (int mt = 0; mt < 4; mt++)
                ldmx4(a[mt][0], a[mt][1], a[mt][2], a[mt][3],
                      Asb + offA[kg] + mt * 2048);
            unsigned bq[4][2];
#pragma unroll
            for (int p = 0; p < 2; p++) {
                unsigned r0, r1, r2, r3;
                ldmx4(r0, r1, r2, r3, Wsb + offB[kg] + p * 2048);
                bq[2*p][0] = r0; bq[2*p][1] = r1;
                bq[2*p+1][0] = r2; bq[2*p+1][1] = r3;
            }
#pragma unroll
            for (int mt = 0; mt < 4; mt++)
#pragma unroll
                for (int nt = 0; nt < 4; nt++)
                    mma16816(cacc[mt][nt], a[mt][0], a[mt][1], a[mt][2], a[mt][3],
                             bq[nt][0], bq[nt][1]);
        }
        __syncthreads();
    }

    // ---- epilogue ----
#pragma unroll
    for (int mt = 0; mt < 4; mt++) {
        int gm = m0 + warp_m*64 + mt*16 + r;
        float rs0 = (EP == 2) ? extra[gm] : 0.f;
        float rs1 = (EP == 2) ? extra[gm + 8] : 0.f;
#pragma unroll
        for (int nt = 0; nt < 4; nt++) {
            int gn = n0 + warp_n*32 + nt*8 + 2*c4;
            float b0 = bias[gn], b1 = bias[gn + 1];
#pragma unroll
            for (int half = 0; half < 2; half++) {
                int row = gm + half*8;
                float v0 = cacc[mt][nt][half*2 + 0] + b0;
                float v1 = cacc[mt][nt][half*2 + 1] + b1;
                if (EP == 1 || EP == 4) {
                    if (EP == 1) {
                        v0 = 0.5f * v0 * (1.f + erff(v0 * 0.70710678118654752f));
                        v1 = 0.5f * v1 * (1.f + erff(v1 * 0.70710678118654752f));
                    }
                    __half* Ch = (__half*)Cc;
                    *(unsigned*)(Ch + (size_t)row * N + gn) = pkh2(v0, v1);
                    continue;
                }
                if (EP == 2) { float rs = half ? rs1 : rs0; v0 *= rs; v1 *= rs; }
                if (EP == 3) {
                    v0 += extra[(size_t)row * N + gn];
                    v1 += extra[(size_t)row * N + gn + 1];
                }
                *(float2*)(Cc + (size_t)row * N + gn) = make_float2(v0, v1);
            }
        }
    }
}

// ============================================================================
// Split-precision fp16 TC GEMM for xi (fp32-accurate), proven R12 version.
// ============================================================================
#define GSM3_BYTES 131072

__global__ __launch_bounds__(256)
void gemm_tc3_kernel(const __half* __restrict__ Ahi, const __half* __restrict__ Alo,
                     const __half* __restrict__ Whi, const __half* __restrict__ Wlo,
                     const float* __restrict__ bias, float* __restrict__ Cc,
                     int M, int N, int K) {
    extern __shared__ float smdyn[];
    uint32_t sbase = smem_u32(smdyn);
    int tid = threadIdx.x;
    int m0 = blockIdx.y * 128, n0 = blockIdx.x * 128;
    int wid = tid >> 5, L = tid & 31;
    int warp_m = wid >> 2;
    int warp_n = wid & 3;
    int r = L >> 2, c4 = L & 3;

    float cacc[4][4][4];
#pragma unroll
    for (int mt = 0; mt < 4; mt++)
#pragma unroll
        for (int nt = 0; nt < 4; nt++)
#pragma unroll
            for (int q = 0; q < 4; q++) cacc[mt][nt][q] = 0.f;

    uint32_t offA[4], offB[4];
    {
        int m_idx = L >> 3;
        uint32_t rA = (uint32_t)(warp_m*64 + (L & 15));
        uint32_t rB = (uint32_t)(warp_n*32 + (m_idx >> 1)*8 + (L & 7));
#pragma unroll
        for (int kg = 0; kg < 4; kg++) {
            offA[kg] = rA * 128 + ((((uint32_t)(2*kg + (L >> 4))) ^ (uint32_t)(L & 7)) << 4);
            offB[kg] = rB * 128 + ((((uint32_t)(2*kg + (m_idx & 1))) ^ (uint32_t)(L & 7)) << 4);
        }
    }

    auto load_tile = [&](int c, int st) {
        const __half* Ah = Ahi + (size_t)m0 * K + c * 64;
        const __half* Al = Alo + (size_t)m0 * K + c * 64;
        const __half* Wh = Whi + (size_t)n0 * K + c * 64;
        const __half* Wl = Wlo + (size_t)n0 * K + c * 64;
        uint32_t base = sbase + st * 65536;
#pragma unroll
        for (int i = 0; i < 4; i++) {
            int idx = tid + 256 * i;
            int row = idx >> 3, g = idx & 7;
            uint32_t so = row * 128 + ((g ^ (row & 7)) << 4);
            size_t go = (size_t)row * K + g * 8;
            cp16(base + so,          Ah + go);
            cp16(base + 16384 + so,  Al + go);
            cp16(base + 32768 + so,  Wh + go);
            cp16(base + 49152 + so,  Wl + go);
        }
        cp_commit();
    };

    const int NC = K >> 6;
    load_tile(0, 0);

    for (int c = 0; c < NC; c++) {
        if (c + 1 < NC) { load_tile(c + 1, (c + 1) & 1); cp_waitg<1>(); }
        else            { cp_waitg<0>(); }
        __syncthreads();

        uint32_t Sb = sbase + (c & 1) * 65536;
#pragma unroll
        for (int kg = 0; kg < 4; kg++) {
            unsigned ah[4][4], al[4][4];
#pragma unroll
            for (int mt = 0; mt < 4; mt++) {
                ldmx4(ah[mt][0], ah[mt][1], ah[mt][2], ah[mt][3],
                      Sb + offA[kg] + mt * 2048);
                ldmx4(al[mt][0], al[mt][1], al[mt][2], al[mt][3],
                      Sb + 16384 + offA[kg] + mt * 2048);
            }
            unsigned bh[4][2], bl[4][2];
#pragma unroll
            for (int p = 0; p < 2; p++) {
                unsigned r0, r1, r2, r3;
                ldmx4(r0, r1, r2, r3, Sb + 32768 + offB[kg] + p * 2048);
                bh[2*p][0] = r0; bh[2*p][1] = r1;
                bh[2*p+1][0] = r2; bh[2*p+1][1] = r3;
                ldmx4(r0, r1, r2, r3, Sb + 49152 + offB[kg] + p * 2048);
                bl[2*p][0] = r0; bl[2*p][1] = r1;
                bl[2*p+1][0] = r2; bl[2*p+1][1] = r3;
            }
#pragma unroll
            for (int mt = 0; mt < 4; mt++)
#pragma unroll
                for (int nt = 0; nt < 4; nt++) {
                    mma16816(cacc[mt][nt], ah[mt][0], ah[mt][1], ah[mt][2], ah[mt][3],
                             bh[nt][0], bh[nt][1]);
                    mma16816(cacc[mt][nt], ah[mt][0], ah[mt][1], ah[mt][2], ah[mt][3],
                             bl[nt][0], bl[nt][1]);
                    mma16816(cacc[mt][nt], al[mt][0], al[mt][1], al[mt][2], al[mt][3],
                             bh[nt][0], bh[nt][1]);
                }
        }
        __syncthreads();
    }

#pragma unroll
    for (int mt = 0; mt < 4; mt++) {
        int gm = m0 + warp_m*64 + mt*16 + r;
#pragma unroll
        for (int nt = 0; nt < 4; nt++) {
            int gn = n0 + warp_n*32 + nt*8 + 2*c4;
            float b0 = bias[gn], b1 = bias[gn + 1];
#pragma unroll
            for (int half = 0; half < 2; half++) {
                int row = gm + half*8;
                *(float2*)(Cc + (size_t)row * N + gn) =
                    make_float2(cacc[mt][nt][half*2] + b0, cacc[mt][nt][half*2+1] + b1);
            }
        }
    }
}

// ---------------- GRU persistent kernel (2 groups; xi software pipeline) ------
#define GRP_CTAS 64
#define CHB 12
__global__ __launch_bounds__(384, 1)
void gru_kernel(const float* __restrict__ xi, const float* __restrict__ Whh,
                const float* __restrict__ bhh) {
    __shared__ float hs[4][Cn];
    __shared__ float gbuf[CHB][3][4];
    int tid = threadIdx.x, w = tid >> 5, lane = tid & 31;
    int grp = blockIdx.x >> 6;          // 0..1
    int cb  = blockIdx.x & 63;
    int c0 = cb * CHB;
    int ch = c0 + w;                    // warp's channel
    int b0 = grp * 4;                   // group's batch base

    ull wp[3][6][2];
#pragma unroll
    for (int g = 0; g < 3; g++)
#pragma unroll
        for (int j = 0; j < 6; j++) {
            float4 v = __ldg((const float4*)(Whh + (size_t)(g*Cn + ch) * Cn) + (j*32 + lane));
            wp[g][j][0] = pk2(v.x, v.y);
            wp[g][j][1] = pk2(v.z, v.w);
        }

    bool is_comb = tid < (4 * CHB);     // 48 combiner threads
    int bcl = 0, ccomb = 0;
    float bhr = 0.f, bhz = 0.f, bhn = 0.f;
    const float* xrow0 = xi;
    if (is_comb) {
        bcl = tid / CHB;                // 0..3 local batch
        ccomb = c0 + tid % CHB;
        bhr = __ldg(bhh + ccomb);
        bhz = __ldg(bhh + Cn + ccomb);
        bhn = __ldg(bhh + 2*Cn + ccomb);
        xrow0 = xi + (size_t)(b0 + bcl) * Tn * G3C + ccomb;
    }
    int gb = b0 + bcl;                  // global batch (comb threads)

    // xi software pipeline: registers hold step-t values, prefetch t+1
    float xr = 0.f, xz = 0.f, xn = 0.f;
    if (is_comb) {
        xr = __ldg(xrow0); xz = __ldg(xrow0 + Cn); xn = __ldg(xrow0 + 2*Cn);
    }

    unsigned* bar = &g_bars[grp * 32];
    unsigned target = GRP_CTAS;
    for (int t = 0; t < Tn; t++) {
        // prefetch xi(t+1) — consumed next iteration (~full step of coverage)
        float xr_n = 0.f, xz_n = 0.f, xn_n = 0.f;
        if (is_comb && (t + 1 < Tn)) {
            const float* xrow = xrow0 + (size_t)(t + 1) * G3C;
            xr_n = __ldg(xrow); xz_n = __ldg(xrow + Cn); xn_n = __ldg(xrow + 2*Cn);
        }

        // stage group's h slice: 4 x 768 floats = 768 float4
        const float4* hp = (const float4*)(g_hstate + b0 * Cn);
        float4* hd = (float4*)&hs[0][0];
        hd[tid]       = __ldcg(hp + tid);
        hd[tid + 384] = __ldcg(hp + tid + 384);
        __syncthreads();

        ull acc2[3][4];
#pragma unroll
        for (int g = 0; g < 3; g++)
#pragma unroll
            for (int b = 0; b < 4; b++) acc2[g][b] = 0ull;

#pragma unroll
        for (int j = 0; j < 6; j++) {
            ull h01[4], h23[4];
#pragma unroll
            for (int b = 0; b < 4; b++) {
                float4 h4 = ((const float4*)&hs[b][0])[j*32 + lane];
                h01[b] = pk2(h4.x, h4.y);
                h23[b] = pk2(h4.z, h4.w);
            }
#pragma unroll
            for (int b = 0; b < 4; b++)
#pragma unroll
                for (int g = 0; g < 3; g++) {
                    fma2(acc2[g][b], wp[g][j][0], h01[b]);
                    fma2(acc2[g][b], wp[g][j][1], h23[b]);
                }
        }
#pragma unroll
        for (int g = 0; g < 3; g++)
#pragma unroll
            for (int b = 0; b < 4; b++) {
                float2 p = upk2(acc2[g][b]);
                float v = p.x + p.y;
#pragma unroll
                for (int off = 16; off > 0; off >>= 1)
                    v += __shfl_xor_sync(0xffffffffu, v, off);
                if (lane == 0) gbuf[w][g][b] = v;
            }
        __syncthreads();

        if (is_comb) {
            int cc = tid % CHB;
            float hr = gbuf[cc][0][bcl] + bhr;
            float hz = gbuf[cc][1][bcl] + bhz;
            float hn = gbuf[cc][2][bcl] + bhn;
            float r = 1.f / (1.f + expf(-(xr + hr)));
            float z = 1.f / (1.f + expf(-(xz + hz)));
            float n = tanhf(xn + r * hn);
            float hold = hs[bcl][ccomb];
            float hnew = (1.f - z) * n + z * hold;
            g_hstate[gb*Cn + ccomb] = hnew;
            g_hrnn[((size_t)gb*Tn + t) * Cn + ccomb] = hnew;
        }
        xr = xr_n; xz = xz_n; xn = xn_n;
        __syncthreads();
        if (tid == 0) {
            red_release_add(bar, 1u);                  // release: prior stores visible
            while (ld_acquire(bar) < target) { }       // tight acquire poll
        }
        target += GRP_CTAS;
        __syncthreads();
    }
}

// ---------------- gate MLP / energy -------------------------------------------
__global__ __launch_bounds__(128)
void energy_kernel(const float* __restrict__ gw1, const float* __restrict__ gb1,
                   const float* __restrict__ gw2, const float* __restrict__ gb2,
                   float* __restrict__ out_energy) {
    int tok = blockIdx.x;
    int tid = threadIdx.x, w = tid >> 5, lane = tid & 31;
    __shared__ float dots[32];
    const float* h = g_hrnn + (size_t)tok * Cn;
#pragma unroll
    for (int jj = 0; jj < 8; jj++) {
        int j = w * 8 + jj;
        const float* wr = gw1 + (size_t)j * Cn;
        float p = 0.f;
        for (int k = lane; k < Cn; k += 32) p += h[k] * wr[k];
#pragma unroll
        for (int off = 16; off > 0; off >>= 1) p += __shfl_xor_sync(0xffffffffu, p, off);
        if (lane == 0) dots[j] = p;
    }
    __syncthreads();
    if (tid == 0) {
        float a = gb2[0];
#pragma unroll
        for (int j = 0; j < 32; j++) a += tanhf(dots[j] + gb1[j]) * gw2[j];
        float e = 1.f / (1.f + expf(-a));
        g_energy[tok] = e;
        out_energy[tok] = e;
        if (e > 0.5f) atomicAdd(&g_active, 1);
    }
}

// ---------------- exact top-k via bitonic sort ---------------------------------
__global__ __launch_bounds__(1024)
void topk_kernel() {
    __shared__ unsigned long long keys[Tn];
    __shared__ int sel[KSEL];
    int b = blockIdx.x, tid = threadIdx.x;
    for (int e = tid; e < Tn; e += 1024) {
        unsigned u = __float_as_uint(g_energy[b*Tn + e]);
        u = (u & 0x80000000u) ? ~u : (u | 0x80000000u);
        keys[e] = ((unsigned long long)u << 32) | (unsigned)(Tn - 1 - e);
    }
    __syncthreads();
    for (int k = 2; k <= Tn; k <<= 1)
        for (int j = k >> 1; j > 0; j >>= 1) {
            int p = tid;
            int e = ((p & ~(j - 1)) << 1) | (p & (j - 1));
            int f = e | j;
            unsigned long long a = keys[e], c = keys[f];
            bool up = ((e & k) == 0);
            bool sw = up ? (a < c) : (a > c);
            if (sw) { keys[e] = c; keys[f] = a; }
            __syncthreads();
        }
    if (tid < KSEL) sel[tid] = Tn - 1 - (int)(keys[tid] & 0xffffffffull);
    __syncthreads();
    for (int k = 2; k <= KSEL; k <<= 1)
        for (int j = k >> 1; j > 0; j >>= 1) {
            if (tid < KSEL/2) {
                int p = tid;
                int e = ((p & ~(j - 1)) << 1) | (p & (j - 1));
                int f = e | j;
                int a = sel[e], c = sel[f];
                bool up = ((e & k) == 0);
                bool sw = up ? (a > c) : (a < c);
                if (sw) { sel[e] = c; sel[f] = a; }
            }
            __syncthreads();
        }
    if (tid < KSEL) g_idx[b*KSEL + tid] = sel[tid];
}

// ---------------- gather selected tokens (store fp16) ---------------------------
__global__ __launch_bounds__(192)
void gather_kernel() {
    int bk = blockIdx.x;
    int b = bk / KSEL;
    int t = g_idx[bk];
    if (threadIdx.x == 0) {
        g_gsel[bk] = g_energy[b*Tn + t];
        g_selmap[b*Tn + t] = bk % KSEL;
    }
    float4 v = ((const float4*)(g_hrnn + ((size_t)b*Tn + t) * Cn))[threadIdx.x];
    uint2 o = make_uint2(pkh2(v.x, v.y), pkh2(v.z, v.w));
    *(uint2*)(g_xsel_h + (size_t)bk * Cn + threadIdx.x * 4) = o;
}

// ============================================================================
// Flash attention, fp16 tensor cores (proven R10 version).
// ============================================================================
#define ASTB 144
#define ATT_TILE_B (64*ASTB)
#define ATT_STAGE  (2*ATT_TILE_B)
#define ATT_SMEM   (2*ATT_STAGE)

__global__ __launch_bounds__(128)
void attn_kernel() {
    extern __shared__ char smc[];
    uint32_t sb = smem_u32(smc);
    int qt = blockIdx.x, bh = blockIdx.y;
    int b = bh / Hn, h = bh % Hn;
    int tid = threadIdx.x, w = tid >> 5, l = tid & 31;
    int g = l >> 2, c = l & 3;
    int q0 = qt * 64;
    const __half* qkv = g_qkv_h + (size_t)b * KSEL * G3C;

    unsigned qw[2][8];
    {
        const unsigned* qlo = (const unsigned*)(qkv + (size_t)(q0 + w*16 + g) * G3C + h*64);
        const unsigned* qhi = (const unsigned*)(qkv + (size_t)(q0 + w*16 + g + 8) * G3C + h*64);
#pragma unroll
        for (int j = 0; j < 8; j++) { qw[0][j] = qlo[4*j + c]; qw[1][j] = qhi[4*j + c]; }
    }

    auto load_kv = [&](int kt, int st) {
        int row = tid >> 1;
        int q = (tid & 1) * 4;
        const __half* Kg = qkv + (size_t)(kt*64 + row) * G3C + Cn + h*64;
        const __half* Vg = qkv + (size_t)(kt*64 + row) * G3C + 2*Cn + h*64;
        uint32_t kb = sb + st*ATT_STAGE + row*ASTB;
        uint32_t vb = kb + ATT_TILE_B;
#pragma unroll
        for (int e = 0; e < 4; e++) {
            cp16(kb + (q+e)*16, Kg + (q+e)*8);
            cp16(vb + (q+e)*16, Vg + (q+e)*8);
        }
        cp_commit();
    };

    float O[8][4];
#pragma unroll
    for (int nt = 0; nt < 8; nt++)
#pragma unroll
        for (int q = 0; q < 4; q++) O[nt][q] = 0.f;
    float m_lo = -1e30f, m_hi = -1e30f, l_lo = 0.f, l_hi = 0.f;

    load_kv(0, 0);

    for (int kt = 0; kt <= qt; kt++) {
        if (kt < qt) { load_kv(kt + 1, (kt + 1) & 1); cp_waitg<1>(); }
        else         { cp_waitg<0>(); }
        __syncthreads();

        uint32_t Ks = sb + (kt & 1) * ATT_STAGE;
        uint32_t Vs = Ks + ATT_TILE_B;

        float s[8][4];
#pragma unroll
        for (int nt = 0; nt < 8; nt++)
#pragma unroll
            for (int q = 0; q < 4; q++) s[nt][q] = 0.f;
#pragma unroll
        for (int kg = 0; kg < 4; kg++) {
            unsigned a0 = qw[0][2*kg], a1 = qw[1][2*kg];
            unsigned a2 = qw[0][2*kg+1], a3 = qw[1][2*kg+1];
#pragma unroll
            for (int np = 0; np < 4; np++) {
                unsigned k0, k1, k2, k3;
                uint32_t addr = Ks + (16*np + ((l & 16) ? 8 : 0) + (l & 7)) * ASTB
                                   + (16*kg + ((l & 8) ? 8 : 0)) * 2;
                ldmx4(k0, k1, k2, k3, addr);
                mma16816(s[2*np],     a0, a1, a2, a3, k0, k1);
                mma16816(s[2*np + 1], a0, a1, a2, a3, k2, k3);
            }
        }
#pragma unroll
        for (int nt = 0; nt < 8; nt++)
#pragma unroll
            for (int q = 0; q < 4; q++) s[nt][q] *= 0.125f;
        if (kt == qt) {
#pragma unroll
            for (int nt = 0; nt < 8; nt++)
#pragma unroll
                for (int e = 0; e < 2; e++) {
                    int col = 8*nt + 2*c + e;
                    if (col > 16*w + g)     s[nt][e]     = -1e30f;
                    if (col > 16*w + g + 8) s[nt][2 + e] = -1e30f;
                }
        }
        float rm_lo = -1e30f, rm_hi = -1e30f;
#pragma unroll
        for (int nt = 0; nt < 8; nt++) {
            rm_lo = fmaxf(rm_lo, fmaxf(s[nt][0], s[nt][1]));
            rm_hi = fmaxf(rm_hi, fmaxf(s[nt][2], s[nt][3]));
        }
#pragma unroll
        for (int off = 1; off <= 2; off <<= 1) {
            rm_lo = fmaxf(rm_lo, __shfl_xor_sync(0xffffffffu, rm_lo, off));
            rm_hi = fmaxf(rm_hi, __shfl_xor_sync(0xffffffffu, rm_hi, off));
        }
        float mn_lo = fmaxf(m_lo, rm_lo), mn_hi = fmaxf(m_hi, rm_hi);
        float al_lo = expf(m_lo - mn_lo), al_hi = expf(m_hi - mn_hi);
        m_lo = mn_lo; m_hi = mn_hi;
        float rs_lo = 0.f, rs_hi = 0.f;
#pragma unroll
        for (int nt = 0; nt < 8; nt++) {
            s[nt][0] = expf(s[nt][0] - mn_lo);
            s[nt][1] = expf(s[nt][1] - mn_lo);
            s[nt][2] = expf(s[nt][2] - mn_hi);
            s[nt][3] = expf(s[nt][3] - mn_hi);
            rs_lo += s[nt][0] + s[nt][1];
            rs_hi += s[nt][2] + s[nt][3];
        }
#pragma unroll
        for (int off = 1; off <= 2; off <<= 1) {
            rs_lo += __shfl_xor_sync(0xffffffffu, rs_lo, off);
            rs_hi += __shfl_xor_sync(0xffffffffu, rs_hi, off);
        }
        l_lo = l_lo * al_lo + rs_lo;
        l_hi = l_hi * al_hi + rs_hi;
#pragma unroll
        for (int nt = 0; nt < 8; nt++) {
            O[nt][0] *= al_lo; O[nt][1] *= al_lo;
            O[nt][2] *= al_hi; O[nt][3] *= al_hi;
        }
        unsigned pa[4][4];
#pragma unroll
        for (int kg = 0; kg < 4; kg++) {
            pa[kg][0] = pkh2(s[2*kg][0],     s[2*kg][1]);
            pa[kg][1] = pkh2(s[2*kg][2],     s[2*kg][3]);
            pa[kg][2] = pkh2(s[2*kg+1][0],   s[2*kg+1][1]);
            pa[kg][3] = pkh2(s[2*kg+1][2],   s[2*kg+1][3]);
        }
#pragma unroll
        for (int kg = 0; kg < 4; kg++) {
#pragma unroll
            for (int np = 0; np < 4; np++) {
                unsigned v0, v1, v2, v3;
                uint32_t addr = Vs + (16*kg + ((l & 8) ? 8 : 0) + (l & 7)) * ASTB
                                   + (16*np + ((l & 16) ? 8 : 0)) * 2;
                ldmx4t(v0, v1, v2, v3, addr);
                mma16816(O[2*np],     pa[kg][0], pa[kg][1], pa[kg][2], pa[kg][3], v0, v1);
                mma16816(O[2*np + 1], pa[kg][0], pa[kg][1], pa[kg][2], pa[kg][3], v2, v3);
            }
        }
        __syncthreads();
    }

    float inv_lo = 1.f / l_lo, inv_hi = 1.f / l_hi;
    int rlo = b * KSEL + q0 + w*16 + g;
#pragma unroll
    for (int nt = 0; nt < 8; nt++) {
        int col = h*64 + 8*nt + 2*c;
        *(unsigned*)(g_y_h + (size_t)rlo * Cn + col) =
            pkh2(O[nt][0] * inv_lo, O[nt][1] * inv_lo);
        *(unsigned*)(g_y_h + (size_t)(rlo + 8) * Cn + col) =
            pkh2(O[nt][2] * inv_hi, O[nt][3] * inv_hi);
    }
}

// ---------------- LayerNorm (fp32 hln + fp16 copy) ------------------------------
__global__ __launch_bounds__(256)
void ln_kernel(const float* __restrict__ g, const float* __restrict__ bb,
               __half* __restrict__ hlnr) {
    __shared__ float xrow[Cn];
    __shared__ float rbuf[16];
    int tok = blockIdx.x, tid = threadIdx.x;
    int b = tok >> 11;
    int sel = g_selmap[tok];
    float s = 0.f, s2 = 0.f;
    for (int c = tid; c < Cn; c += 256) {
        float v = g_hrnn[(size_t)tok*Cn + c];
        if (sel >= 0) v += g_weighted[((size_t)(b*KSEL + sel))*Cn + c];
        xrow[c] = v; s += v; s2 += v*v;
    }
#pragma unroll
    for (int off = 16; off > 0; off >>= 1) {
        s  += __shfl_xor_sync(0xffffffffu, s, off);
        s2 += __shfl_xor_sync(0xffffffffu, s2, off);
    }
    int w = tid >> 5;
    if ((tid & 31) == 0) { rbuf[w] = s; rbuf[8 + w] = s2; }
    __syncthreads();
    if (tid == 0) {
        float S = 0.f, S2 = 0.f;
        for (int i = 0; i < 8; i++) { S += rbuf[i]; S2 += rbuf[8 + i]; }
        float mu = S / (float)Cn;
        float var = S2 / (float)Cn - mu*mu;
        rbuf[0] = mu; rbuf[1] = rsqrtf(var + 1e-5f);
    }
    __syncthreads();
    float mu = rbuf[0], inv = rbuf[1];
    for (int c = tid; c < Cn; c += 256) {
        float v = (xrow[c] - mu) * inv * g[c] + bb[c];
        g_hln[(size_t)tok*Cn + c] = v;
        hlnr[(size_t)tok*Cn + c] = __float2half_rn(v);
    }
}

// ---------------- finalize ------------------------------------------------------
__global__ void finalize_kernel(float* out) {
    out[(size_t)BT*Cn + BT] = (float)g_active;
}

// ---------------- launcher ------------------------------------------------------
extern "C" void kernel_launch(void* const* d_in, const int* in_sizes, int n_in,
                              void* d_out, int out_size) {
    const float* x      = (const float*)d_in[0];
    const float* W_ih   = (const float*)d_in[1];
    const float* W_hh   = (const float*)d_in[2];
    const float* b_ih   = (const float*)d_in[3];
    const float* b_hh   = (const float*)d_in[4];
    const float* gate_w1= (const float*)d_in[5];
    const float* gate_b1= (const float*)d_in[6];
    const float* gate_w2= (const float*)d_in[7];
    const float* gate_b2= (const float*)d_in[8];
    const float* qkv_w  = (const float*)d_in[9];
    const float* qkv_b  = (const float*)d_in[10];
    const float* proj_w = (const float*)d_in[11];
    const float* proj_b = (const float*)d_in[12];
    const float* ln_g   = (const float*)d_in[13];
    const float* ln_b   = (const float*)d_in[14];
    const float* ffn_w1 = (const float*)d_in[15];
    const float* ffn_b1 = (const float*)d_in[16];
    const float* ffn_w2 = (const float*)d_in[17];
    const float* ffn_b2 = (const float*)d_in[18];
    float* out = (float*)d_out;

    float *p_xi, *p_weighted, *p_hln;
    __half *p_xsel, *p_qkvh, *p_y, *p_mid, *p_wscr, *p_xhi, *p_xlo, *p_whi, *p_wlo;
    cudaGetSymbolAddress((void**)&p_xi,       g_xi);
    cudaGetSymbolAddress((void**)&p_xsel,     g_xsel_h);
    cudaGetSymbolAddress((void**)&p_qkvh,     g_qkv_h);
    cudaGetSymbolAddress((void**)&p_y,        g_y_h);
    cudaGetSymbolAddress((void**)&p_weighted, g_weighted);
    cudaGetSymbolAddress((void**)&p_hln,      g_hln);
    cudaGetSymbolAddress((void**)&p_mid,      g_mid_h);
    cudaGetSymbolAddress((void**)&p_wscr,     g_wscr_h);
    cudaGetSymbolAddress((void**)&p_xhi,      g_xhi);
    cudaGetSymbolAddress((void**)&p_xlo,      g_xlo);
    cudaGetSymbolAddress((void**)&p_whi,      g_wih_hi);
    cudaGetSymbolAddress((void**)&p_wlo,      g_wih_lo);
    float* p_gsel; cudaGetSymbolAddress((void**)&p_gsel, g_gsel);
    float* p_energy_out = out + (size_t)BT*Cn;
    __half* p_hlnr = (__half*)p_xi;

    cudaFuncSetAttribute(attn_kernel, cudaFuncAttributeMaxDynamicSharedMemorySize, ATT_SMEM);
    cudaFuncSetAttribute(gemm_tc_kernel<1>, cudaFuncAttributeMaxDynamicSharedMemorySize, GSM_BYTES);
    cudaFuncSetAttribute(gemm_tc_kernel<2>, cudaFuncAttributeMaxDynamicSharedMemorySize, GSM_BYTES);
    cudaFuncSetAttribute(gemm_tc_kernel<3>, cudaFuncAttributeMaxDynamicSharedMemorySize, GSM_BYTES);
    cudaFuncSetAttribute(gemm_tc_kernel<4>, cudaFuncAttributeMaxDynamicSharedMemorySize, GSM_BYTES);
    cudaFuncSetAttribute(gemm_tc3_kernel,   cudaFuncAttributeMaxDynamicSharedMemorySize, GSM3_BYTES);

    // 0) init
    init_kernel<<<64, 256>>>();

    // 1) weights -> fp16; x/W_ih -> split fp16
    cvtw_kernel<<<(WTOTAL + 255)/256, 256>>>(qkv_w, proj_w, ffn_w1, ffn_w2);
    cvtx_kernel<<<(BT*Cn + 255)/256, 256>>>(x, W_ih);

    // 2) xi = x @ W_ih^T + b_ih  (split-precision fp16 TC, fp32-accurate)
    gemm_tc3_kernel<<<dim3(G3C/128, BT/128), 256, GSM3_BYTES>>>(
        p_xhi, p_xlo, p_whi, p_wlo, b_ih, p_xi, BT, G3C, Cn);

    // 3) GRU scan (2 groups, xi register pipeline)
    gru_kernel<<<2*GRP_CTAS, 384>>>(p_xi, W_hh, b_hh);

    // 4) energy
    energy_kernel<<<BT, 128>>>(gate_w1, gate_b1, gate_w2, gate_b2, p_energy_out);

    // 5) top-k
    topk_kernel<<<Bn, 1024>>>();

    // 6) gather (fp16 xsel)
    gather_kernel<<<BKn, 192>>>();

    // 7) qkv GEMM (fp16 in, fp16 out)
    gemm_tc_kernel<4><<<dim3(G3C/128, BKn/128), 256, GSM_BYTES>>>(
        p_xsel, p_wscr + WOFF_QKV, qkv_b, nullptr, (float*)p_qkvh, BKn, G3C, Cn);

    // 8) attention (tensor-core flash, fp16 y)
    attn_kernel<<<dim3(KSEL/64, Bn*Hn), 128, ATT_SMEM>>>();

    // 9) proj GEMM (row-scale)
    gemm_tc_kernel<2><<<dim3(Cn/128, BKn/128), 256, GSM_BYTES>>>(
        p_y, p_wscr + WOFF_PROJ, proj_b, p_gsel, p_weighted, BKn, Cn, Cn);

    // 10) LayerNorm
    ln_kernel<<<BT, 256>>>(ln_g, ln_b, p_hlnr);

    // 11) ffn1 GEMM (gelu -> fp16 mid)
    gemm_tc_kernel<1><<<dim3(DFF/128, BT/128), 256, GSM_BYTES>>>(
        (const __half*)p_hlnr, p_wscr + WOFF_FFN1, ffn_b1, nullptr, (float*)p_mid, BT, DFF, Cn);

    // 12) ffn2 GEMM (residual) -> out
    gemm_tc_kernel<3><<<dim3(Cn/128, BT/128), 256, GSM_BYTES>>>(
        p_mid, p_wscr + WOFF_FFN2, ffn_b2, p_hln, out, BT, Cn, DFF);

    // 13) active count
    finalize_kernel<<<1, 1>>>(out);

    (void)in_sizes; (void)n_in; (void)out_size;
}

// round 17
// speedup vs baseline: 1.0368x; 1.0285x over previous
#include <cuda_runtime.h>
#include <cuda_fp16.h>
#include <math.h>
#include <stdint.h>

#define Bn 8
#define Tn 2048
#define Cn 768
#define Hn 12
#define KSEL 1024
#define DFF 3072
#define BT (Bn*Tn)      /* 16384 */
#define BKn (Bn*KSEL)   /* 8192 */
#define G3C (3*Cn)      /* 2304 */

typedef unsigned long long ull;

// ---------------- f32x2 packed helpers --------------------------------------
__device__ __forceinline__ ull pk2(float x, float y) {
    ull r; asm("mov.b64 %0, {%1, %2};" : "=l"(r) : "f"(x), "f"(y)); return r;
}
__device__ __forceinline__ void fma2(ull &acc, ull a, ull b) {
    asm("fma.rn.f32x2 %0, %1, %2, %0;" : "+l"(acc) : "l"(a), "l"(b));
}
__device__ __forceinline__ float2 upk2(ull v) {
    float2 r; asm("mov.b64 {%0, %1}, %2;" : "=f"(r.x), "=f"(r.y) : "l"(v)); return r;
}
__device__ __forceinline__ unsigned pkh2(float a, float b) {
    __half2 h = __floats2half2_rn(a, b);
    return *reinterpret_cast<unsigned*>(&h);
}

// ---------------- cp.async / smem helpers ------------------------------------
__device__ __forceinline__ uint32_t smem_u32(const void* p) {
    uint32_t a; asm("{ .reg .u64 t; cvta.to.shared.u64 t, %1; cvt.u32.u64 %0, t; }"
                    : "=r"(a) : "l"(p));
    return a;
}
__device__ __forceinline__ void cp16(uint32_t saddr, const void* gaddr) {
    asm volatile("cp.async.cg.shared.global [%0], [%1], 16;"
                 :: "r"(saddr), "l"(__cvta_generic_to_global(gaddr)));
}
__device__ __forceinline__ void cp_commit() { asm volatile("cp.async.commit_group;"); }
template<int N>
__device__ __forceinline__ void cp_waitg() {
    asm volatile("cp.async.wait_group %0;" :: "n"(N) : "memory");
}
__device__ __forceinline__ void ldmx4(unsigned &r0, unsigned &r1, unsigned &r2,
                                      unsigned &r3, uint32_t addr) {
    asm volatile("ldmatrix.sync.aligned.m8n8.x4.shared.b16 {%0,%1,%2,%3}, [%4];"
                 : "=r"(r0), "=r"(r1), "=r"(r2), "=r"(r3) : "r"(addr));
}
__device__ __forceinline__ void ldmx4t(unsigned &r0, unsigned &r1, unsigned &r2,
                                       unsigned &r3, uint32_t addr) {
    asm volatile("ldmatrix.sync.aligned.m8n8.x4.trans.shared.b16 {%0,%1,%2,%3}, [%4];"
                 : "=r"(r0), "=r"(r1), "=r"(r2), "=r"(r3) : "r"(addr));
}
__device__ __forceinline__ void mma16816(float* d, unsigned a0, unsigned a1,
                                         unsigned a2, unsigned a3,
                                         unsigned b0, unsigned b1) {
    asm volatile("mma.sync.aligned.m16n8k16.row.col.f32.f16.f16.f32 "
                 "{%0,%1,%2,%3}, {%4,%5,%6,%7}, {%8,%9}, {%0,%1,%2,%3};"
                 : "+f"(d[0]), "+f"(d[1]), "+f"(d[2]), "+f"(d[3])
                 : "r"(a0), "r"(a1), "r"(a2), "r"(a3), "r"(b0), "r"(b1));
}
// release-reduce arrival + acquire poll (GPU scope)
__device__ __forceinline__ void red_release_add(unsigned* addr, unsigned v) {
    asm volatile("red.release.gpu.global.add.u32 [%0], %1;"
                 :: "l"(addr), "r"(v) : "memory");
}
__device__ __forceinline__ unsigned ld_acquire(const unsigned* addr) {
    unsigned v;
    asm volatile("ld.acquire.gpu.global.u32 %0, [%1];" : "=r"(v) : "l"(addr) : "memory");
    return v;
}

// ---------------- scratch -----------------------------------------------------
__device__ float g_xi[(size_t)BT*G3C];     // xi; later reused as half hlnr
__device__ float g_hrnn[(size_t)BT*Cn];
__device__ float g_hstate[Bn*Cn];
__device__ float g_energy[BT];
__device__ int   g_idx[BKn];
__device__ int   g_selmap[BT];
__device__ __half g_xsel_h[(size_t)BKn*Cn];
__device__ float g_gsel[BKn];
__device__ __half g_qkv_h[(size_t)BKn*G3C];
__device__ __half g_y_h[(size_t)BKn*Cn];
__device__ float g_weighted[(size_t)BKn*Cn];
__device__ float g_hln[(size_t)BT*Cn];
__device__ __half g_mid_h[(size_t)BT*DFF];
__device__ __half g_wscr_h[7077888];       // half weights: qkv|proj|ffn1|ffn2
__device__ __half g_xhi[(size_t)BT*Cn];
__device__ __half g_xlo[(size_t)BT*Cn];
__device__ __half g_wih_hi[(size_t)G3C*Cn];
__device__ __half g_wih_lo[(size_t)G3C*Cn];
__device__ unsigned g_bars[64];            // 2 group barriers, 128B apart
__device__ int g_active;

#define WOFF_QKV  0
#define WOFF_PROJ 1769472
#define WOFF_FFN1 2359296
#define WOFF_FFN2 4718592
#define WTOTAL    7077888

// ---------------- init --------------------------------------------------------
__global__ void init_kernel() {
    int tid = blockIdx.x * blockDim.x + threadIdx.x;
    if (tid == 0) g_active = 0;
    if (tid < 64) g_bars[tid] = 0u;
    for (int i = tid; i < Bn*Cn; i += gridDim.x*blockDim.x) g_hstate[i] = 0.f;
    for (int i = tid; i < BT;    i += gridDim.x*blockDim.x) g_selmap[i] = -1;
}

// ---------------- weight conversion to fp16 ------------------------------------
__global__ __launch_bounds__(256)
void cvtw_kernel(const float* __restrict__ qkvw, const float* __restrict__ projw,
                 const float* __restrict__ w1, const float* __restrict__ w2) {
    int i = blockIdx.x * 256 + threadIdx.x;
    if (i >= WTOTAL) return;
    float v;
    if (i < WOFF_PROJ)       v = qkvw[i - WOFF_QKV];
    else if (i < WOFF_FFN1)  v = projw[i - WOFF_PROJ];
    else if (i < WOFF_FFN2)  v = w1[i - WOFF_FFN1];
    else                     v = w2[i - WOFF_FFN2];
    g_wscr_h[i] = __float2half_rn(v);
}

// ---------------- split-precision conversion (x and W_ih) ----------------------
__global__ __launch_bounds__(256)
void cvtx_kernel(const float* __restrict__ x, const float* __restrict__ wih) {
    int i = blockIdx.x * 256 + threadIdx.x;
    const int NX = BT * Cn;
    const int NW = G3C * Cn;
    if (i < NX) {
        float v = x[i];
        __half hi = __float2half_rn(v);
        g_xhi[i] = hi;
        g_xlo[i] = __float2half_rn(v - __half2float(hi));
    }
    if (i < NW) {
        float v = wih[i];
        __half hi = __float2half_rn(v);
        g_wih_hi[i] = hi;
        g_wih_lo[i] = __float2half_rn(v - __half2float(hi));
    }
}

// ============================================================================
// FP16 tensor-core GEMM (mma.sync m16n8k16, cp.async 3-stage, ldmatrix frags):
// EP: 0 none, 1 gelu->half store, 2 row-scale, 3 residual, 4 plain->half store
// ============================================================================
#define GSM_BYTES 98304

template<int EP>
__global__ __launch_bounds__(256, 2)
void gemm_tc_kernel(const __half* __restrict__ A, const __half* __restrict__ W,
                    const float* __restrict__ bias, const float* __restrict__ extra,
                    float* __restrict__ Cc, int M, int N, int K) {
    extern __shared__ float smdyn[];
    uint32_t sbase = smem_u32(smdyn);
    int tid = threadIdx.x;
    int m0 = blockIdx.y * 128, n0 = blockIdx.x * 128;
    int wid = tid >> 5, L = tid & 31;
    int warp_m = wid >> 2;
    int warp_n = wid & 3;
    int r = L >> 2, c4 = L & 3;

    float cacc[4][4][4];
#pragma unroll
    for (int mt = 0; mt < 4; mt++)
#pragma unroll
        for (int nt = 0; nt < 4; nt++)
#pragma unroll
            for (int q = 0; q < 4; q++) cacc[mt][nt][q] = 0.f;

    uint32_t offA[4], offB[4];
    {
        int m_idx = L >> 3;
        uint32_t rA = (uint32_t)(warp_m*64 + (L & 15));
        uint32_t rB = (uint32_t)(warp_n*32 + (m_idx >> 1)*8 + (L & 7));
#pragma unroll
        for (int kg = 0; kg < 4; kg++) {
            offA[kg] = rA * 128 + ((((uint32_t)(2*kg + (L >> 4))) ^ (uint32_t)(L & 7)) << 4);
            offB[kg] = rB * 128 + ((((uint32_t)(2*kg + (m_idx & 1))) ^ (uint32_t)(L & 7)) << 4);
        }
    }

    auto load_tile = [&](int c, int st) {
        const __half* Ag = A + (size_t)m0 * K + c * 64;
        const __half* Wg = W + (size_t)n0 * K + c * 64;
        uint32_t ab = sbase + st * 32768;
        uint32_t wb = ab + 16384;
#pragma unroll
        for (int i = 0; i < 4; i++) {
            int idx = tid + 256 * i;
            int row = idx >> 3, g = idx & 7;
            uint32_t so = row * 128 + ((g ^ (row & 7)) << 4);
            cp16(ab + so, Ag + (size_t)row * K + g * 8);
            cp16(wb + so, Wg + (size_t)row * K + g * 8);
        }
        cp_commit();
    };

    const int NC = K >> 6;
    load_tile(0, 0);
    if (NC > 1) load_tile(1, 1);

    int st = 0, st2 = (NC > 2) ? 2 : 0;
    for (int c = 0; c < NC; c++) {
        if (c + 2 < NC) {
            load_tile(c + 2, st2);
            st2 = (st2 == 2) ? 0 : st2 + 1;
            cp_waitg<2>();
        } else if (c + 1 < NC) {
            cp_waitg<1>();
        } else {
            cp_waitg<0>();
        }
        __syncthreads();

        uint32_t Asb = sbase + st * 32768;
        uint32_t Wsb = Asb + 16384;
        st = (st == 2) ? 0 : st + 1;
#pragma unroll
        for (int kg = 0; kg < 4; kg++) {
            unsigned a[4][4];
#pragma unroll
            for (int mt = 0; mt < 4; mt++)
                ldmx4(a[mt][0], a[mt][1], a[mt][2], a[mt][3],
                      Asb + offA[kg] + mt * 2048);
            unsigned bq[4][2];
#pragma unroll
            for (int p = 0; p < 2; p++) {
                unsigned r0, r1, r2, r3;
                ldmx4(r0, r1, r2, r3, Wsb + offB[kg] + p * 2048);
                bq[2*p][0] = r0; bq[2*p][1] = r1;
                bq[2*p+1][0] = r2; bq[2*p+1][1] = r3;
            }
#pragma unroll
            for (int mt = 0; mt < 4; mt++)
#pragma unroll
                for (int nt = 0; nt < 4; nt++)
                    mma16816(cacc[mt][nt], a[mt][0], a[mt][1], a[mt][2], a[mt][3],
                             bq[nt][0], bq[nt][1]);
        }
        __syncthreads();
    }

    // ---- epilogue ----
#pragma unroll
    for (int mt = 0; mt < 4; mt++) {
        int gm = m0 + warp_m*64 + mt*16 + r;
        float rs0 = (EP == 2) ? extra[gm] : 0.f;
        float rs1 = (EP == 2) ? extra[gm + 8] : 0.f;
#pragma unroll
        for (int nt = 0; nt < 4; nt++) {
            int gn = n0 + warp_n*32 + nt*8 + 2*c4;
            float b0 = bias[gn], b1 = bias[gn + 1];
#pragma unroll
            for (int half = 0; half < 2; half++) {
                int row = gm + half*8;
                float v0 = cacc[mt][nt][half*2 + 0] + b0;
                float v1 = cacc[mt][nt][half*2 + 1] + b1;
                if (EP == 1 || EP == 4) {
                    if (EP == 1) {
                        v0 = 0.5f * v0 * (1.f + erff(v0 * 0.70710678118654752f));
                        v1 = 0.5f * v1 * (1.f + erff(v1 * 0.70710678118654752f));
                    }
                    __half* Ch = (__half*)Cc;
                    *(unsigned*)(Ch + (size_t)row * N + gn) = pkh2(v0, v1);
                    continue;
                }
                if (EP == 2) { float rs = half ? rs1 : rs0; v0 *= rs; v1 *= rs; }
                if (EP == 3) {
                    v0 += extra[(size_t)row * N + gn];
                    v1 += extra[(size_t)row * N + gn + 1];
                }
                *(float2*)(Cc + (size_t)row * N + gn) = make_float2(v0, v1);
            }
        }
    }
}

// ============================================================================
// Split-precision fp16 TC GEMM for xi (fp32-accurate), proven R12 version.
// ============================================================================
#define GSM3_BYTES 131072

__global__ __launch_bounds__(256)
void gemm_tc3_kernel(const __half* __restrict__ Ahi, const __half* __restrict__ Alo,
                     const __half* __restrict__ Whi, const __half* __restrict__ Wlo,
                     const float* __restrict__ bias, float* __restrict__ Cc,
                     int M, int N, int K) {
    extern __shared__ float smdyn[];
    uint32_t sbase = smem_u32(smdyn);
    int tid = threadIdx.x;
    int m0 = blockIdx.y * 128, n0 = blockIdx.x * 128;
    int wid = tid >> 5, L = tid & 31;
    int warp_m = wid >> 2;
    int warp_n = wid & 3;
    int r = L >> 2, c4 = L & 3;

    float cacc[4][4][4];
#pragma unroll
    for (int mt = 0; mt < 4; mt++)
#pragma unroll
        for (int nt = 0; nt < 4; nt++)
#pragma unroll
            for (int q = 0; q < 4; q++) cacc[mt][nt][q] = 0.f;

    uint32_t offA[4], offB[4];
    {
        int m_idx = L >> 3;
        uint32_t rA = (uint32_t)(warp_m*64 + (L & 15));
        uint32_t rB = (uint32_t)(warp_n*32 + (m_idx >> 1)*8 + (L & 7));
#pragma unroll
        for (int kg = 0; kg < 4; kg++) {
            offA[kg] = rA * 128 + ((((uint32_t)(2*kg + (L >> 4))) ^ (uint32_t)(L & 7)) << 4);
            offB[kg] = rB * 128 + ((((uint32_t)(2*kg + (m_idx & 1))) ^ (uint32_t)(L & 7)) << 4);
        }
    }

    auto load_tile = [&](int c, int st) {
        const __half* Ah = Ahi + (size_t)m0 * K + c * 64;
        const __half* Al = Alo + (size_t)m0 * K + c * 64;
        const __half* Wh = Whi + (size_t)n0 * K + c * 64;
        const __half* Wl = Wlo + (size_t)n0 * K + c * 64;
        uint32_t base = sbase + st * 65536;
#pragma unroll
        for (int i = 0; i < 4; i++) {
            int idx = tid + 256 * i;
            int row = idx >> 3, g = idx & 7;
            uint32_t so = row * 128 + ((g ^ (row & 7)) << 4);
            size_t go = (size_t)row * K + g * 8;
            cp16(base + so,          Ah + go);
            cp16(base + 16384 + so,  Al + go);
            cp16(base + 32768 + so,  Wh + go);
            cp16(base + 49152 + so,  Wl + go);
        }
        cp_commit();
    };

    const int NC = K >> 6;
    load_tile(0, 0);

    for (int c = 0; c < NC; c++) {
        if (c + 1 < NC) { load_tile(c + 1, (c + 1) & 1); cp_waitg<1>(); }
        else            { cp_waitg<0>(); }
        __syncthreads();

        uint32_t Sb = sbase + (c & 1) * 65536;
#pragma unroll
        for (int kg = 0; kg < 4; kg++) {
            unsigned ah[4][4], al[4][4];
#pragma unroll
            for (int mt = 0; mt < 4; mt++) {
                ldmx4(ah[mt][0], ah[mt][1], ah[mt][2], ah[mt][3],
                      Sb + offA[kg] + mt * 2048);
                ldmx4(al[mt][0], al[mt][1], al[mt][2], al[mt][3],
                      Sb + 16384 + offA[kg] + mt * 2048);
            }
            unsigned bh[4][2], bl[4][2];
#pragma unroll
            for (int p = 0; p < 2; p++) {
                unsigned r0, r1, r2, r3;
                ldmx4(r0, r1, r2, r3, Sb + 32768 + offB[kg] + p * 2048);
                bh[2*p][0] = r0; bh[2*p][1] = r1;
                bh[2*p+1][0] = r2; bh[2*p+1][1] = r3;
                ldmx4(r0, r1, r2, r3, Sb + 49152 + offB[kg] + p * 2048);
                bl[2*p][0] = r0; bl[2*p][1] = r1;
                bl[2*p+1][0] = r2; bl[2*p+1][1] = r3;
            }
#pragma unroll
            for (int mt = 0; mt < 4; mt++)
#pragma unroll
                for (int nt = 0; nt < 4; nt++) {
                    mma16816(cacc[mt][nt], ah[mt][0], ah[mt][1], ah[mt][2], ah[mt][3],
                             bh[nt][0], bh[nt][1]);
                    mma16816(cacc[mt][nt], ah[mt][0], ah[mt][1], ah[mt][2], ah[mt][3],
                             bl[nt][0], bl[nt][1]);
                    mma16816(cacc[mt][nt], al[mt][0], al[mt][1], al[mt][2], al[mt][3],
                             bh[nt][0], bh[nt][1]);
                }
        }
        __syncthreads();
    }

#pragma unroll
    for (int mt = 0; mt < 4; mt++) {
        int gm = m0 + warp_m*64 + mt*16 + r;
#pragma unroll
        for (int nt = 0; nt < 4; nt++) {
            int gn = n0 + warp_n*32 + nt*8 + 2*c4;
            float b0 = bias[gn], b1 = bias[gn + 1];
#pragma unroll
            for (int half = 0; half < 2; half++) {
                int row = gm + half*8;
                *(float2*)(Cc + (size_t)row * N + gn) =
                    make_float2(cacc[mt][nt][half*2] + b0, cacc[mt][nt][half*2+1] + b1);
            }
        }
    }
}

// ---------------- GRU persistent kernel (deferred archive stores) -------------
#define GRP_CTAS 64
#define CHB 12
__global__ __launch_bounds__(384, 1)
void gru_kernel(const float* __restrict__ xi, const float* __restrict__ Whh,
                const float* __restrict__ bhh) {
    __shared__ float hs[4][Cn];
    __shared__ float gbuf[CHB][3][4];
    int tid = threadIdx.x, w = tid >> 5, lane = tid & 31;
    int grp = blockIdx.x >> 6;          // 0..1
    int cb  = blockIdx.x & 63;
    int c0 = cb * CHB;
    int ch = c0 + w;                    // warp's channel
    int b0 = grp * 4;                   // group's batch base

    ull wp[3][6][2];
#pragma unroll
    for (int g = 0; g < 3; g++)
#pragma unroll
        for (int j = 0; j < 6; j++) {
            float4 v = __ldg((const float4*)(Whh + (size_t)(g*Cn + ch) * Cn) + (j*32 + lane));
            wp[g][j][0] = pk2(v.x, v.y);
            wp[g][j][1] = pk2(v.z, v.w);
        }

    bool is_comb = tid < (4 * CHB);     // 48 combiner threads
    int bcl = 0, ccomb = 0;
    float bhr = 0.f, bhz = 0.f, bhn = 0.f;
    const float* xrow0 = xi;
    if (is_comb) {
        bcl = tid / CHB;                // 0..3 local batch
        ccomb = c0 + tid % CHB;
        bhr = __ldg(bhh + ccomb);
        bhz = __ldg(bhh + Cn + ccomb);
        bhn = __ldg(bhh + 2*Cn + ccomb);
        xrow0 = xi + (size_t)(b0 + bcl) * Tn * G3C + ccomb;
    }
    int gb = b0 + bcl;                  // global batch (comb threads)
    float* hrnn0 = g_hrnn + (size_t)gb * Tn * Cn + ccomb;

    // xi software pipeline: registers hold step-t values, prefetch t+1
    float xr = 0.f, xz = 0.f, xn = 0.f;
    if (is_comb) {
        xr = __ldg(xrow0); xz = __ldg(xrow0 + Cn); xn = __ldg(xrow0 + 2*Cn);
    }

    unsigned* bar = &g_bars[grp * 32];
    unsigned target = GRP_CTAS;
    for (int t = 0; t < Tn; t++) {
        // prefetch xi(t+1) — consumed next iteration
        float xr_n = 0.f, xz_n = 0.f, xn_n = 0.f;
        if (is_comb && (t + 1 < Tn)) {
            const float* xrow = xrow0 + (size_t)(t + 1) * G3C;
            xr_n = __ldg(xrow); xz_n = __ldg(xrow + Cn); xn_n = __ldg(xrow + 2*Cn);
        }

        // stage group's h slice: 4 x 768 floats = 768 float4
        const float4* hp = (const float4*)(g_hstate + b0 * Cn);
        float4* hd = (float4*)&hs[0][0];
        hd[tid]       = __ldcg(hp + tid);
        hd[tid + 384] = __ldcg(hp + tid + 384);
        __syncthreads();

        ull acc2[3][4];
#pragma unroll
        for (int g = 0; g < 3; g++)
#pragma unroll
            for (int b = 0; b < 4; b++) acc2[g][b] = 0ull;

#pragma unroll
        for (int j = 0; j < 6; j++) {
            ull h01[4], h23[4];
#pragma unroll
            for (int b = 0; b < 4; b++) {
                float4 h4 = ((const float4*)&hs[b][0])[j*32 + lane];
                h01[b] = pk2(h4.x, h4.y);
                h23[b] = pk2(h4.z, h4.w);
            }
#pragma unroll
            for (int b = 0; b < 4; b++)
#pragma unroll
                for (int g = 0; g < 3; g++) {
                    fma2(acc2[g][b], wp[g][j][0], h01[b]);
                    fma2(acc2[g][b], wp[g][j][1], h23[b]);
                }
        }
#pragma unroll
        for (int g = 0; g < 3; g++)
#pragma unroll
            for (int b = 0; b < 4; b++) {
                float2 p = upk2(acc2[g][b]);
                float v = p.x + p.y;
#pragma unroll
                for (int off = 16; off > 0; off >>= 1)
                    v += __shfl_xor_sync(0xffffffffu, v, off);
                if (lane == 0) gbuf[w][g][b] = v;
            }
        __syncthreads();

        float hnew = 0.f;
        if (is_comb) {
            int cc = tid % CHB;
            float hr = gbuf[cc][0][bcl] + bhr;
            float hz = gbuf[cc][1][bcl] + bhz;
            float hn = gbuf[cc][2][bcl] + bhn;
            float r = 1.f / (1.f + expf(-(xr + hr)));
            float z = 1.f / (1.f + expf(-(xz + hz)));
            float n = tanhf(xn + r * hn);
            float hold = hs[bcl][ccomb];
            hnew = (1.f - z) * n + z * hold;
            g_hstate[gb*Cn + ccomb] = hnew;   // critical-path store only
        }
        xr = xr_n; xz = xz_n; xn = xn_n;
        __syncthreads();
        if (tid == 0) red_release_add(bar, 1u);   // release: hstate visible
        // archive store OFF the fence path — overlaps the poll window
        if (is_comb) hrnn0[(size_t)t * Cn] = hnew;
        if (tid == 0) {
            while (ld_acquire(bar) < target) { }
        }
        target += GRP_CTAS;
        __syncthreads();
    }
}

// ---------------- gate MLP / energy -------------------------------------------
__global__ __launch_bounds__(128)
void energy_kernel(const float* __restrict__ gw1, const float* __restrict__ gb1,
                   const float* __restrict__ gw2, const float* __restrict__ gb2,
                   float* __restrict__ out_energy) {
    int tok = blockIdx.x;
    int tid = threadIdx.x, w = tid >> 5, lane = tid & 31;
    __shared__ float dots[32];
    const float* h = g_hrnn + (size_t)tok * Cn;
#pragma unroll
    for (int jj = 0; jj < 8; jj++) {
        int j = w * 8 + jj;
        const float* wr = gw1 + (size_t)j * Cn;
        float p = 0.f;
        for (int k = lane; k < Cn; k += 32) p += h[k] * wr[k];
#pragma unroll
        for (int off = 16; off > 0; off >>= 1) p += __shfl_xor_sync(0xffffffffu, p, off);
        if (lane == 0) dots[j] = p;
    }
    __syncthreads();
    if (tid == 0) {
        float a = gb2[0];
#pragma unroll
        for (int j = 0; j < 32; j++) a += tanhf(dots[j] + gb1[j]) * gw2[j];
        float e = 1.f / (1.f + expf(-a));
        g_energy[tok] = e;
        out_energy[tok] = e;
        if (e > 0.5f) atomicAdd(&g_active, 1);
    }
}

// ---------------- exact top-k via bitonic sort ---------------------------------
__global__ __launch_bounds__(1024)
void topk_kernel() {
    __shared__ unsigned long long keys[Tn];
    __shared__ int sel[KSEL];
    int b = blockIdx.x, tid = threadIdx.x;
    for (int e = tid; e < Tn; e += 1024) {
        unsigned u = __float_as_uint(g_energy[b*Tn + e]);
        u = (u & 0x80000000u) ? ~u : (u | 0x80000000u);
        keys[e] = ((unsigned long long)u << 32) | (unsigned)(Tn - 1 - e);
    }
    __syncthreads();
    for (int k = 2; k <= Tn; k <<= 1)
        for (int j = k >> 1; j > 0; j >>= 1) {
            int p = tid;
            int e = ((p & ~(j - 1)) << 1) | (p & (j - 1));
            int f = e | j;
            unsigned long long a = keys[e], c = keys[f];
            bool up = ((e & k) == 0);
            bool sw = up ? (a < c) : (a > c);
            if (sw) { keys[e] = c; keys[f] = a; }
            __syncthreads();
        }
    if (tid < KSEL) sel[tid] = Tn - 1 - (int)(keys[tid] & 0xffffffffull);
    __syncthreads();
    for (int k = 2; k <= KSEL; k <<= 1)
        for (int j = k >> 1; j > 0; j >>= 1) {
            if (tid < KSEL/2) {
                int p = tid;
                int e = ((p & ~(j - 1)) << 1) | (p & (j - 1));
                int f = e | j;
                int a = sel[e], c = sel[f];
                bool up = ((e & k) == 0);
                bool sw = up ? (a > c) : (a < c);
                if (sw) { sel[e] = c; sel[f] = a; }
            }
            __syncthreads();
        }
    if (tid < KSEL) g_idx[b*KSEL + tid] = sel[tid];
}

// ---------------- gather selected tokens (store fp16) ---------------------------
__global__ __launch_bounds__(192)
void gather_kernel() {
    int bk = blockIdx.x;
    int b = bk / KSEL;
    int t = g_idx[bk];
    if (threadIdx.x == 0) {
        g_gsel[bk] = g_energy[b*Tn + t];
        g_selmap[b*Tn + t] = bk % KSEL;
    }
    float4 v = ((const float4*)(g_hrnn + ((size_t)b*Tn + t) * Cn))[threadIdx.x];
    uint2 o = make_uint2(pkh2(v.x, v.y), pkh2(v.z, v.w));
    *(uint2*)(g_xsel_h + (size_t)bk * Cn + threadIdx.x * 4) = o;
}

// ============================================================================
// Flash attention, fp16 tensor cores (proven R10 version).
// ============================================================================
#define ASTB 144
#define ATT_TILE_B (64*ASTB)
#define ATT_STAGE  (2*ATT_TILE_B)
#define ATT_SMEM   (2*ATT_STAGE)

__global__ __launch_bounds__(128)
void attn_kernel() {
    extern __shared__ char smc[];
    uint32_t sb = smem_u32(smc);
    int qt = blockIdx.x, bh = blockIdx.y;
    int b = bh / Hn, h = bh % Hn;
    int tid = threadIdx.x, w = tid >> 5, l = tid & 31;
    int g = l >> 2, c = l & 3;
    int q0 = qt * 64;
    const __half* qkv = g_qkv_h + (size_t)b * KSEL * G3C;

    unsigned qw[2][8];
    {
        const unsigned* qlo = (const unsigned*)(qkv + (size_t)(q0 + w*16 + g) * G3C + h*64);
        const unsigned* qhi = (const unsigned*)(qkv + (size_t)(q0 + w*16 + g + 8) * G3C + h*64);
#pragma unroll
        for (int j = 0; j < 8; j++) { qw[0][j] = qlo[4*j + c]; qw[1][j] = qhi[4*j + c]; }
    }

    auto load_kv = [&](int kt, int st) {
        int row = tid >> 1;
        int q = (tid & 1) * 4;
        const __half* Kg = qkv + (size_t)(kt*64 + row) * G3C + Cn + h*64;
        const __half* Vg = qkv + (size_t)(kt*64 + row) * G3C + 2*Cn + h*64;
        uint32_t kb = sb + st*ATT_STAGE + row*ASTB;
        uint32_t vb = kb + ATT_TILE_B;
#pragma unroll
        for (int e = 0; e < 4; e++) {
            cp16(kb + (q+e)*16, Kg + (q+e)*8);
            cp16(vb + (q+e)*16, Vg + (q+e)*8);
        }
        cp_commit();
    };

    float O[8][4];
#pragma unroll
    for (int nt = 0; nt < 8; nt++)
#pragma unroll
        for (int q = 0; q < 4; q++) O[nt][q] = 0.f;
    float m_lo = -1e30f, m_hi = -1e30f, l_lo = 0.f, l_hi = 0.f;

    load_kv(0, 0);

    for (int kt = 0; kt <= qt; kt++) {
        if (kt < qt) { load_kv(kt + 1, (kt + 1) & 1); cp_waitg<1>(); }
        else         { cp_waitg<0>(); }
        __syncthreads();

        uint32_t Ks = sb + (kt & 1) * ATT_STAGE;
        uint32_t Vs = Ks + ATT_TILE_B;

        float s[8][4];
#pragma unroll
        for (int nt = 0; nt < 8; nt++)
#pragma unroll
            for (int q = 0; q < 4; q++) s[nt][q] = 0.f;
#pragma unroll
        for (int kg = 0; kg < 4; kg++) {
            unsigned a0 = qw[0][2*kg], a1 = qw[1][2*kg];
            unsigned a2 = qw[0][2*kg+1], a3 = qw[1][2*kg+1];
#pragma unroll
            for (int np = 0; np < 4; np++) {
                unsigned k0, k1, k2, k3;
                uint32_t addr = Ks + (16*np + ((l & 16) ? 8 : 0) + (l & 7)) * ASTB
                                   + (16*kg + ((l & 8) ? 8 : 0)) * 2;
                ldmx4(k0, k1, k2, k3, addr);
                mma16816(s[2*np],     a0, a1, a2, a3, k0, k1);
                mma16816(s[2*np + 1], a0, a1, a2, a3, k2, k3);
            }
        }
#pragma unroll
        for (int nt = 0; nt < 8; nt++)
#pragma unroll
            for (int q = 0; q < 4; q++) s[nt][q] *= 0.125f;
        if (kt == qt) {
#pragma unroll
            for (int nt = 0; nt < 8; nt++)
#pragma unroll
                for (int e = 0; e < 2; e++) {
                    int col = 8*nt + 2*c + e;
                    if (col > 16*w + g)     s[nt][e]     = -1e30f;
                    if (col > 16*w + g + 8) s[nt][2 + e] = -1e30f;
                }
        }
        float rm_lo = -1e30f, rm_hi = -1e30f;
#pragma unroll
        for (int nt = 0; nt < 8; nt++) {
            rm_lo = fmaxf(rm_lo, fmaxf(s[nt][0], s[nt][1]));
            rm_hi = fmaxf(rm_hi, fmaxf(s[nt][2], s[nt][3]));
        }
#pragma unroll
        for (int off = 1; off <= 2; off <<= 1) {
            rm_lo = fmaxf(rm_lo, __shfl_xor_sync(0xffffffffu, rm_lo, off));
            rm_hi = fmaxf(rm_hi, __shfl_xor_sync(0xffffffffu, rm_hi, off));
        }
        float mn_lo = fmaxf(m_lo, rm_lo), mn_hi = fmaxf(m_hi, rm_hi);
        float al_lo = expf(m_lo - mn_lo), al_hi = expf(m_hi - mn_hi);
        m_lo = mn_lo; m_hi = mn_hi;
        float rs_lo = 0.f, rs_hi = 0.f;
#pragma unroll
        for (int nt = 0; nt < 8; nt++) {
            s[nt][0] = expf(s[nt][0] - mn_lo);
            s[nt][1] = expf(s[nt][1] - mn_lo);
            s[nt][2] = expf(s[nt][2] - mn_hi);
            s[nt][3] = expf(s[nt][3] - mn_hi);
            rs_lo += s[nt][0] + s[nt][1];
            rs_hi += s[nt][2] + s[nt][3];
        }
#pragma unroll
        for (int off = 1; off <= 2; off <<= 1) {
            rs_lo += __shfl_xor_sync(0xffffffffu, rs_lo, off);
            rs_hi += __shfl_xor_sync(0xffffffffu, rs_hi, off);
        }
        l_lo = l_lo * al_lo + rs_lo;
        l_hi = l_hi * al_hi + rs_hi;
#pragma unroll
        for (int nt = 0; nt < 8; nt++) {
            O[nt][0] *= al_lo; O[nt][1] *= al_lo;
            O[nt][2] *= al_hi; O[nt][3] *= al_hi;
        }
        unsigned pa[4][4];
#pragma unroll
        for (int kg = 0; kg < 4; kg++) {
            pa[kg][0] = pkh2(s[2*kg][0],     s[2*kg][1]);
            pa[kg][1] = pkh2(s[2*kg][2],     s[2*kg][3]);
            pa[kg][2] = pkh2(s[2*kg+1][0],   s[2*kg+1][1]);
            pa[kg][3] = pkh2(s[2*kg+1][2],   s[2*kg+1][3]);
        }
#pragma unroll
        for (int kg = 0; kg < 4; kg++) {
#pragma unroll
            for (int np = 0; np < 4; np++) {
                unsigned v0, v1, v2, v3;
                uint32_t addr = Vs + (16*kg + ((l & 8) ? 8 : 0) + (l & 7)) * ASTB
                                   + (16*np + ((l & 16) ? 8 : 0)) * 2;
                ldmx4t(v0, v1, v2, v3, addr);
                mma16816(O[2*np],     pa[kg][0], pa[kg][1], pa[kg][2], pa[kg][3], v0, v1);
                mma16816(O[2*np + 1], pa[kg][0], pa[kg][1], pa[kg][2], pa[kg][3], v2, v3);
            }
        }
        __syncthreads();
    }

    float inv_lo = 1.f / l_lo, inv_hi = 1.f / l_hi;
    int rlo = b * KSEL + q0 + w*16 + g;
#pragma unroll
    for (int nt = 0; nt < 8; nt++) {
        int col = h*64 + 8*nt + 2*c;
        *(unsigned*)(g_y_h + (size_t)rlo * Cn + col) =
            pkh2(O[nt][0] * inv_lo, O[nt][1] * inv_lo);
        *(unsigned*)(g_y_h + (size_t)(rlo + 8) * Cn + col) =
            pkh2(O[nt][2] * inv_hi, O[nt][3] * inv_hi);
    }
}

// ---------------- LayerNorm (fp32 hln + fp16 copy) ------------------------------
__global__ __launch_bounds__(256)
void ln_kernel(const float* __restrict__ g, const float* __restrict__ bb,
               __half* __restrict__ hlnr) {
    __shared__ float xrow[Cn];
    __shared__ float rbuf[16];
    int tok = blockIdx.x, tid = threadIdx.x;
    int b = tok >> 11;
    int sel = g_selmap[tok];
    float s = 0.f, s2 = 0.f;
    for (int c = tid; c < Cn; c += 256) {
        float v = g_hrnn[(size_t)tok*Cn + c];
        if (sel >= 0) v += g_weighted[((size_t)(b*KSEL + sel))*Cn + c];
        xrow[c] = v; s += v; s2 += v*v;
    }
#pragma unroll
    for (int off = 16; off > 0; off >>= 1) {
        s  += __shfl_xor_sync(0xffffffffu, s, off);
        s2 += __shfl_xor_sync(0xffffffffu, s2, off);
    }
    int w = tid >> 5;
    if ((tid & 31) == 0) { rbuf[w] = s; rbuf[8 + w] = s2; }
    __syncthreads();
    if (tid == 0) {
        float S = 0.f, S2 = 0.f;
        for (int i = 0; i < 8; i++) { S += rbuf[i]; S2 += rbuf[8 + i]; }
        float mu = S / (float)Cn;
        float var = S2 / (float)Cn - mu*mu;
        rbuf[0] = mu; rbuf[1] = rsqrtf(var + 1e-5f);
    }
    __syncthreads();
    float mu = rbuf[0], inv = rbuf[1];
    for (int c = tid; c < Cn; c += 256) {
        float v = (xrow[c] - mu) * inv * g[c] + bb[c];
        g_hln[(size_t)tok*Cn + c] = v;
        hlnr[(size_t)tok*Cn + c] = __float2half_rn(v);
    }
}

// ---------------- finalize ------------------------------------------------------
__global__ void finalize_kernel(float* out) {
    out[(size_t)BT*Cn + BT] = (float)g_active;
}

// ---------------- launcher ------------------------------------------------------
extern "C" void kernel_launch(void* const* d_in, const int* in_sizes, int n_in,
                              void* d_out, int out_size) {
    const float* x      = (const float*)d_in[0];
    const float* W_ih   = (const float*)d_in[1];
    const float* W_hh   = (const float*)d_in[2];
    const float* b_ih   = (const float*)d_in[3];
    const float* b_hh   = (const float*)d_in[4];
    const float* gate_w1= (const float*)d_in[5];
    const float* gate_b1= (const float*)d_in[6];
    const float* gate_w2= (const float*)d_in[7];
    const float* gate_b2= (const float*)d_in[8];
    const float* qkv_w  = (const float*)d_in[9];
    const float* qkv_b  = (const float*)d_in[10];
    const float* proj_w = (const float*)d_in[11];
    const float* proj_b = (const float*)d_in[12];
    const float* ln_g   = (const float*)d_in[13];
    const float* ln_b   = (const float*)d_in[14];
    const float* ffn_w1 = (const float*)d_in[15];
    const float* ffn_b1 = (const float*)d_in[16];
    const float* ffn_w2 = (const float*)d_in[17];
    const float* ffn_b2 = (const float*)d_in[18];
    float* out = (float*)d_out;

    float *p_xi, *p_weighted, *p_hln;
    __half *p_xsel, *p_qkvh, *p_y, *p_mid, *p_wscr, *p_xhi, *p_xlo, *p_whi, *p_wlo;
    cudaGetSymbolAddress((void**)&p_xi,       g_xi);
    cudaGetSymbolAddress((void**)&p_xsel,     g_xsel_h);
    cudaGetSymbolAddress((void**)&p_qkvh,     g_qkv_h);
    cudaGetSymbolAddress((void**)&p_y,        g_y_h);
    cudaGetSymbolAddress((void**)&p_weighted, g_weighted);
    cudaGetSymbolAddress((void**)&p_hln,      g_hln);
    cudaGetSymbolAddress((void**)&p_mid,      g_mid_h);
    cudaGetSymbolAddress((void**)&p_wscr,     g_wscr_h);
    cudaGetSymbolAddress((void**)&p_xhi,      g_xhi);
    cudaGetSymbolAddress((void**)&p_xlo,      g_xlo);
    cudaGetSymbolAddress((void**)&p_whi,      g_wih_hi);
    cudaGetSymbolAddress((void**)&p_wlo,      g_wih_lo);
    float* p_gsel; cudaGetSymbolAddress((void**)&p_gsel, g_gsel);
    float* p_energy_out = out + (size_t)BT*Cn;
    __half* p_hlnr = (__half*)p_xi;

    cudaFuncSetAttribute(attn_kernel, cudaFuncAttributeMaxDynamicSharedMemorySize, ATT_SMEM);
    cudaFuncSetAttribute(gemm_tc_kernel<1>, cudaFuncAttributeMaxDynamicSharedMemorySize, GSM_BYTES);
    cudaFuncSetAttribute(gemm_tc_kernel<2>, cudaFuncAttributeMaxDynamicSharedMemorySize, GSM_BYTES);
    cudaFuncSetAttribute(gemm_tc_kernel<3>, cudaFuncAttributeMaxDynamicSharedMemorySize, GSM_BYTES);
    cudaFuncSetAttribute(gemm_tc_kernel<4>, cudaFuncAttributeMaxDynamicSharedMemorySize, GSM_BYTES);
    cudaFuncSetAttribute(gemm_tc3_kernel,   cudaFuncAttributeMaxDynamicSharedMemorySize, GSM3_BYTES);

    // 0) init
    init_kernel<<<64, 256>>>();

    // 1) weights -> fp16; x/W_ih -> split fp16
    cvtw_kernel<<<(WTOTAL + 255)/256, 256>>>(qkv_w, proj_w, ffn_w1, ffn_w2);
    cvtx_kernel<<<(BT*Cn + 255)/256, 256>>>(x, W_ih);

    // 2) xi = x @ W_ih^T + b_ih  (split-precision fp16 TC, fp32-accurate)
    gemm_tc3_kernel<<<dim3(G3C/128, BT/128), 256, GSM3_BYTES>>>(
        p_xhi, p_xlo, p_whi, p_wlo, b_ih, p_xi, BT, G3C, Cn);

    // 3) GRU scan (2 groups, deferred archive stores)
    gru_kernel<<<2*GRP_CTAS, 384>>>(p_xi, W_hh, b_hh);

    // 4) energy
    energy_kernel<<<BT, 128>>>(gate_w1, gate_b1, gate_w2, gate_b2, p_energy_out);

    // 5) top-k
    topk_kernel<<<Bn, 1024>>>();

    // 6) gather (fp16 xsel)
    gather_kernel<<<BKn, 192>>>();

    // 7) qkv GEMM (fp16 in, fp16 out)
    gemm_tc_kernel<4><<<dim3(G3C/128, BKn/128), 256, GSM_BYTES>>>(
        p_xsel, p_wscr + WOFF_QKV, qkv_b, nullptr, (float*)p_qkvh, BKn, G3C, Cn);

    // 8) attention (tensor-core flash, fp16 y)
    attn_kernel<<<dim3(KSEL/64, Bn*Hn), 128, ATT_SMEM>>>();

    // 9) proj GEMM (row-scale)
    gemm_tc_kernel<2><<<dim3(Cn/128, BKn/128), 256, GSM_BYTES>>>(
        p_y, p_wscr + WOFF_PROJ, proj_b, p_gsel, p_weighted, BKn, Cn, Cn);

    // 10) LayerNorm
    ln_kernel<<<BT, 256>>>(ln_g, ln_b, p_hlnr);

    // 11) ffn1 GEMM (gelu -> fp16 mid)
    gemm_tc_kernel<1><<<dim3(DFF/128, BT/128), 256, GSM_BYTES>>>(
        (const __half*)p_hlnr, p_wscr + WOFF_FFN1, ffn_b1, nullptr, (float*)p_mid, BT, DFF, Cn);

    // 12) ffn2 GEMM (residual) -> out
    gemm_tc_kernel<3><<<dim3(Cn/128, BT/128), 256, GSM_BYTES>>>(
        p_mid, p_wscr + WOFF_FFN2, ffn_b2, p_hln, out, BT, Cn, DFF);

    // 13) active count
    finalize_kernel<<<1, 1>>>(out);

    (void)in_sizes; (void)n_in; (void)out_size;
}